// round 12
// baseline (speedup 1.0000x reference)
#include <cuda_runtime.h>
#include <cuda_bf16.h>
#include <math.h>
#include <stdint.h>

// Problem constants
constexpr int BATCH = 16, NCROP = 10, BNB = 160, T = 256, D = 1024, CC = 512;
constexpr int H = 4, DH = 128, LDEP = 2;
constexpr int MALL = BNB * T;               // 40960 rows
constexpr float EPS = 1e-5f;

// ---------------- device scratch (static, no allocation) ----------------
__device__ __align__(16) __nv_bfloat16 g_xph[(size_t)BNB * (T + 2) * D];
__device__ __align__(16) __nv_bfloat16 g_xpl[(size_t)BNB * (T + 2) * D];
__device__ __align__(16) __nv_bfloat16 g_bteh[CC * 3 * D];
__device__ __align__(16) __nv_bfloat16 g_btel[CC * 3 * D];
__device__ __align__(16) __nv_bfloat16 g_zh[(size_t)MALL * CC];
__device__ __align__(16) __nv_bfloat16 g_zl[(size_t)MALL * CC];
__device__ __align__(16) __nv_bfloat16 g_f1h[(size_t)MALL * CC];
__device__ __align__(16) __nv_bfloat16 g_f1l[(size_t)MALL * CC];
__device__ __align__(16) __nv_bfloat16 g_Oh[(size_t)MALL * 2 * CC];
__device__ __align__(16) __nv_bfloat16 g_Ol[(size_t)MALL * 2 * CC];
__device__ __align__(16) __nv_bfloat16 g_qkvth[(size_t)MALL * 4 * CC];
__device__ __align__(16) __nv_bfloat16 g_qkvtl[(size_t)MALL * 4 * CC];
__device__ __align__(16) __nv_bfloat16 g_Sh[(size_t)BNB * H * T * T];
__device__ __align__(16) __nv_bfloat16 g_Sl[(size_t)BNB * H * T * T];
__device__ __align__(16) __nv_bfloat16 g_vth[(size_t)BNB * H * DH * T];
__device__ __align__(16) __nv_bfloat16 g_vtl[(size_t)BNB * H * DH * T];
__device__ __align__(16) __nv_bfloat16 g_tth[(size_t)BNB * H * DH * T];
__device__ __align__(16) __nv_bfloat16 g_ttl[(size_t)BNB * H * DH * T];
__device__ __align__(16) __nv_bfloat16 g_a2h[T * T];
__device__ __align__(16) __nv_bfloat16 g_a2l[T * T];
__device__ __align__(16) __nv_bfloat16 g_wqkvh[LDEP * 4 * CC * CC];
__device__ __align__(16) __nv_bfloat16 g_wqkvl[LDEP * 4 * CC * CC];
__device__ __align__(16) __nv_bfloat16 g_woh[LDEP * CC * 2 * CC];
__device__ __align__(16) __nv_bfloat16 g_wol[LDEP * CC * 2 * CC];
__device__ __align__(16) __nv_bfloat16 g_wf1h[LDEP * CC * CC];
__device__ __align__(16) __nv_bfloat16 g_wf1l[LDEP * CC * CC];
__device__ __align__(16) __nv_bfloat16 g_wf2h[LDEP * CC * CC];
__device__ __align__(16) __nv_bfloat16 g_wf2l[LDEP * CC * CC];
// fp32 buffers
__device__ __align__(16) float g_h[(size_t)MALL * CC];
__device__ __align__(16) float g_S[(size_t)BNB * H * T * T];
__device__ float g_arow[T];
__device__ float g_w1t[CC * 32];
__device__ float g_w2t[32 * 16];
__device__ float g_score[MALL];
__device__ float g_dist[MALL];

// ---------------- helpers ----------------
__device__ __forceinline__ void split2(float x, __nv_bfloat16& hi, __nv_bfloat16& lo) {
    hi = __float2bfloat16(x);
    lo = __float2bfloat16(x - __bfloat162float(hi));
}
__device__ __forceinline__ uint32_t smem_u32(const void* p) {
    uint32_t a;
    asm("{ .reg .u64 t; cvta.to.shared.u64 t, %1; cvt.u32.u64 %0, t; }" : "=r"(a) : "l"(p));
    return a;
}
__device__ __forceinline__ void cp16(uint32_t dst, const void* src) {
    asm volatile("cp.async.cg.shared.global [%0], [%1], 16;" :: "r"(dst), "l"(src));
}
__device__ __forceinline__ void cp_commit() {
    asm volatile("cp.async.commit_group;" ::: "memory");
}
template<int N>
__device__ __forceinline__ void cp_wait() {
    asm volatile("cp.async.wait_group %0;" :: "n"(N) : "memory");
}
__device__ __forceinline__ void ldsm4(uint32_t& r0, uint32_t& r1, uint32_t& r2, uint32_t& r3, uint32_t addr) {
    asm volatile("ldmatrix.sync.aligned.m8n8.x4.shared.b16 {%0,%1,%2,%3}, [%4];"
                 : "=r"(r0), "=r"(r1), "=r"(r2), "=r"(r3) : "r"(addr));
}
__device__ __forceinline__ void mma16816(float* c, const uint32_t* a, const uint32_t* b) {
    asm volatile(
        "mma.sync.aligned.m16n8k16.row.col.f32.bf16.bf16.f32 "
        "{%0,%1,%2,%3}, {%4,%5,%6,%7}, {%8,%9}, {%0,%1,%2,%3};"
        : "+f"(c[0]), "+f"(c[1]), "+f"(c[2]), "+f"(c[3])
        : "r"(a[0]), "r"(a[1]), "r"(a[2]), "r"(a[3]), "r"(b[0]), "r"(b[1]));
}

// ================= big HMMA split-bf16 GEMM: C(M,N) = A(M,K) @ Bt(N,K)^T =================
// CTA 128(M) x 256(N), 8 warps of 64x64 (2x4), BK=32, 3-stage cp.async, 1 sync/chunk,
// TERM-MAJOR mma ordering (16 independent MMAs between same-acc reuse). 1 CTA/SM.
// EPI: 1 +bias relu fp32; 2 +bias +C fp32; 3 +bias gelu split; 4 plain split.
constexpr int BSTG = 61440;                   // (128 + 128 + 256 + 256) rows x 80B
constexpr int MMB_SMEM = 3 * BSTG;            // 184320

template<int EPI>
__global__ void __launch_bounds__(256, 1) mma_gemm_big(
    const __nv_bfloat16* __restrict__ Ah, const __nv_bfloat16* __restrict__ Al,
    int lda, int convA,
    const __nv_bfloat16* __restrict__ Bh, const __nv_bfloat16* __restrict__ Bl,
    int ldb, int K,
    float* __restrict__ C,
    __nv_bfloat16* __restrict__ Ch, __nv_bfloat16* __restrict__ Cl,
    int ldc, const float* __restrict__ bias)
{
    extern __shared__ __align__(1024) char smem[];
    const uint32_t sbase = smem_u32(smem);
    const int tid = threadIdx.x, lane = tid & 31, wid = tid >> 5;
    const int m0 = blockIdx.y * 128, n0 = blockIdx.x * 256;
    const int wm = (wid & 1) * 64, wn = (wid >> 1) * 64;

    // load plan: A (h+l): 2 threads/row, 2 cp16 each; B (h+l): 1 thread/row, 4 cp16 each
    const int arow = tid >> 1, ahalf = tid & 1;
    size_t aro = (size_t)(m0 + arow) * lda + (convA ? (size_t)((m0 + arow) >> 8) * 2048 : 0) + ahalf * 16;
    const __nv_bfloat16* pAh = Ah + aro;
    const __nv_bfloat16* pAl = Al + aro;
    const uint32_t aoff = (uint32_t)(arow * 80 + ahalf * 32);
    size_t bro = (size_t)(n0 + tid) * ldb;
    const __nv_bfloat16* pBh = Bh + bro;
    const __nv_bfloat16* pBl = Bl + bro;
    const uint32_t boff = (uint32_t)(20480 + tid * 80);

    const int nc = K / 32;

    auto load_stage = [&](int c, int slot) {
        uint32_t s = sbase + (uint32_t)(slot * BSTG);
        int k0 = c * 32;
        cp16(s + aoff, pAh + k0);           cp16(s + aoff + 16, pAh + k0 + 8);
        cp16(s + 10240 + aoff, pAl + k0);   cp16(s + 10240 + aoff + 16, pAl + k0 + 8);
        cp16(s + boff,      pBh + k0);      cp16(s + boff + 16, pBh + k0 + 8);
        cp16(s + boff + 32, pBh + k0 + 16); cp16(s + boff + 48, pBh + k0 + 24);
        cp16(s + 20480 + boff,      pBl + k0);      cp16(s + 20480 + boff + 16, pBl + k0 + 8);
        cp16(s + 20480 + boff + 32, pBl + k0 + 16); cp16(s + 20480 + boff + 48, pBl + k0 + 24);
    };

    load_stage(0, 0); cp_commit();
    load_stage(1, 1); cp_commit();

    float acc[4][8][4] = {};
    const int lrowA = lane & 15, lkA = (lane >> 4) << 3;
    const int lrowB = ((lane >> 4) << 3) + (lane & 7), lkB = ((lane >> 3) & 1) << 3;

    int slot = 0;
    for (int c = 0; c < nc; c++) {
        if (c + 1 < nc) cp_wait<1>(); else cp_wait<0>();
        __syncthreads();
        if (c + 2 < nc) {
            int ns = slot + 2; if (ns >= 3) ns -= 3;
            load_stage(c + 2, ns);
            cp_commit();
        }
        uint32_t sa = sbase + (uint32_t)(slot * BSTG);
        #pragma unroll
        for (int kk2 = 0; kk2 < 2; kk2++) {
            const int kk = kk2 * 16;
            uint32_t ah[4][4], al4[4][4];
            #pragma unroll
            for (int mt = 0; mt < 4; mt++) {
                uint32_t ra = sa + (uint32_t)((wm + mt * 16 + lrowA) * 80 + (kk + lkA) * 2);
                ldsm4(ah[mt][0], ah[mt][1], ah[mt][2], ah[mt][3], ra);
                ldsm4(al4[mt][0], al4[mt][1], al4[mt][2], al4[mt][3], ra + 10240);
            }
            #pragma unroll
            for (int half2 = 0; half2 < 2; half2++) {
                uint32_t bh[4][2], bl[4][2];
                #pragma unroll
                for (int np = 0; np < 2; np++) {
                    uint32_t rb = sa + (uint32_t)(20480 + (wn + half2 * 32 + np * 16 + lrowB) * 80 + (kk + lkB) * 2);
                    uint32_t h0, h1, h2, h3;
                    ldsm4(h0, h1, h2, h3, rb);
                    bh[np * 2][0] = h0; bh[np * 2][1] = h1;
                    bh[np * 2 + 1][0] = h2; bh[np * 2 + 1][1] = h3;
                    ldsm4(h0, h1, h2, h3, rb + 20480);
                    bl[np * 2][0] = h0; bl[np * 2][1] = h1;
                    bl[np * 2 + 1][0] = h2; bl[np * 2 + 1][1] = h3;
                }
                // TERM-MAJOR: all hi*hi, then hi*lo, then lo*hi (16 apart on same acc)
                #pragma unroll
                for (int mt = 0; mt < 4; mt++)
                    #pragma unroll
                    for (int j = 0; j < 4; j++)
                        mma16816(acc[mt][half2 * 4 + j], ah[mt], bh[j]);
                #pragma unroll
                for (int mt = 0; mt < 4; mt++)
                    #pragma unroll
                    for (int j = 0; j < 4; j++)
                        mma16816(acc[mt][half2 * 4 + j], ah[mt], bl[j]);
                #pragma unroll
                for (int mt = 0; mt < 4; mt++)
                    #pragma unroll
                    for (int j = 0; j < 4; j++)
                        mma16816(acc[mt][half2 * 4 + j], al4[mt], bh[j]);
            }
        }
        if (++slot == 3) slot = 0;
    }

    // ---- epilogue ----
    const int qr = lane >> 2, qc = (lane & 3) * 2;
    #pragma unroll
    for (int mt = 0; mt < 4; mt++) {
        #pragma unroll
        for (int hrow = 0; hrow < 2; hrow++) {
            int grow = m0 + wm + mt * 16 + qr + hrow * 8;
            #pragma unroll
            for (int nt = 0; nt < 8; nt++) {
                int gcol = n0 + wn + nt * 8 + qc;
                float v0 = acc[mt][nt][hrow * 2 + 0];
                float v1 = acc[mt][nt][hrow * 2 + 1];
                if (EPI == 1 || EPI == 2 || EPI == 3) { v0 += bias[gcol]; v1 += bias[gcol + 1]; }
                if (EPI == 1) { v0 = fmaxf(v0, 0.f); v1 = fmaxf(v1, 0.f); }
                if (EPI == 3) {
                    v0 = 0.5f * v0 * (1.f + erff(v0 * 0.70710678118654752f));
                    v1 = 0.5f * v1 * (1.f + erff(v1 * 0.70710678118654752f));
                }
                size_t off = (size_t)grow * ldc + gcol;
                if (EPI == 3 || EPI == 4) {
                    __nv_bfloat16 bh0, bl0, bh1, bl1;
                    split2(v0, bh0, bl0); split2(v1, bh1, bl1);
                    __nv_bfloat162 ph; ph.x = bh0; ph.y = bh1;
                    __nv_bfloat162 pl; pl.x = bl0; pl.y = bl1;
                    *reinterpret_cast<__nv_bfloat162*>(Ch + off) = ph;
                    *reinterpret_cast<__nv_bfloat162*>(Cl + off) = pl;
                } else {
                    if (EPI == 2) {
                        float2 old = *reinterpret_cast<const float2*>(C + off);
                        v0 += old.x; v1 += old.y;
                    }
                    float2 o; o.x = v0; o.y = v1;
                    *reinterpret_cast<float2*>(C + off) = o;
                }
            }
        }
    }
}

// ================= attention HMMA split-bf16 GEMM (128x128 CTA, 64x32 warps, 2 CTA/SM) =================
constexpr int LDS = 40;
constexpr int TILE_B = 128 * LDS * 2;
constexpr int STAGE_B = 4 * TILE_B;
constexpr int MM_SMEM = 2 * STAGE_B;

template<int EPI>  // 0 fp32 store (alpha); 4 plain split
__global__ void __launch_bounds__(256, 2) mma_gemm(
    const __nv_bfloat16* __restrict__ Ah, const __nv_bfloat16* __restrict__ Al,
    int lda,
    const __nv_bfloat16* __restrict__ Bh, const __nv_bfloat16* __restrict__ Bl,
    int ldb, int K, float alpha,
    float* __restrict__ C,
    __nv_bfloat16* __restrict__ Ch, __nv_bfloat16* __restrict__ Cl,
    int ldc,
    int H2, long long sA1, long long sA2, long long sB1, long long sB2,
    long long sC1, long long sC2)
{
    extern __shared__ __align__(1024) char smem[];
    const uint32_t sbase = smem_u32(smem);
    const int tid = threadIdx.x, lane = tid & 31, wid = tid >> 5;
    const int bz = blockIdx.z;
    const int b1 = bz / H2, b2 = bz - b1 * H2;
    const size_t abase = (size_t)b1 * sA1 + (size_t)b2 * sA2;
    const size_t bbase = (size_t)b1 * sB1 + (size_t)b2 * sB2;
    const size_t cbase = (size_t)b1 * sC1 + (size_t)b2 * sC2;
    const int m0 = blockIdx.y * 128, n0 = blockIdx.x * 128;
    const int wm = (wid & 1) * 64, wn = (wid >> 1) * 32;

    const __nv_bfloat16* srcp[8];
    uint32_t doff[8];
    #pragma unroll
    for (int q = 0; q < 8; q++) {
        int ci = q * 256 + tid;
        int u = ci >> 9;
        int r = (ci >> 2) & 127;
        int c16 = ci & 3;
        doff[q] = (uint32_t)(u * TILE_B + r * (LDS * 2) + c16 * 16);
        if (u < 2) {
            size_t ro = abase + (size_t)(m0 + r) * lda + c16 * 8;
            srcp[q] = (u == 0 ? Ah : Al) + ro;
        } else {
            size_t ro = bbase + (size_t)(n0 + r) * ldb + c16 * 8;
            srcp[q] = (u == 2 ? Bh : Bl) + ro;
        }
    }

    const int nc = K / 32;
    #pragma unroll
    for (int q = 0; q < 8; q++) cp16(sbase + doff[q], srcp[q]);
    cp_commit();

    float acc[4][4][4] = {};
    const int lrowA = lane & 15, lkA = (lane >> 4) << 3;
    const int lrowB = ((lane >> 4) << 3) + (lane & 7), lkB = ((lane >> 3) & 1) << 3;

    for (int c = 0; c < nc; c++) {
        cp_wait<0>();
        __syncthreads();
        if (c + 1 < nc) {
            uint32_t st = sbase + (uint32_t)(((c + 1) & 1) * STAGE_B);
            int k0 = (c + 1) * 32;
            #pragma unroll
            for (int q = 0; q < 8; q++) cp16(st + doff[q], srcp[q] + k0);
            cp_commit();
        }
        uint32_t sa = sbase + (uint32_t)((c & 1) * STAGE_B);
        #pragma unroll
        for (int kk2 = 0; kk2 < 2; kk2++) {
            const int kk = kk2 * 16;
            uint32_t ah[4][4], alr[4][4], bh[4][2], bl[4][2];
            #pragma unroll
            for (int mt = 0; mt < 4; mt++) {
                uint32_t ra = sa + (uint32_t)((wm + mt * 16 + lrowA) * (LDS * 2) + (kk + lkA) * 2);
                ldsm4(ah[mt][0], ah[mt][1], ah[mt][2], ah[mt][3], ra);
                ldsm4(alr[mt][0], alr[mt][1], alr[mt][2], alr[mt][3], ra + TILE_B);
            }
            #pragma unroll
            for (int np = 0; np < 2; np++) {
                uint32_t rb = sa + (uint32_t)(2 * TILE_B + (wn + np * 16 + lrowB) * (LDS * 2) + (kk + lkB) * 2);
                uint32_t h0, h1, h2, h3;
                ldsm4(h0, h1, h2, h3, rb);
                bh[np * 2][0] = h0; bh[np * 2][1] = h1;
                bh[np * 2 + 1][0] = h2; bh[np * 2 + 1][1] = h3;
                ldsm4(h0, h1, h2, h3, rb + TILE_B);
                bl[np * 2][0] = h0; bl[np * 2][1] = h1;
                bl[np * 2 + 1][0] = h2; bl[np * 2 + 1][1] = h3;
            }
            #pragma unroll
            for (int mt = 0; mt < 4; mt++)
                #pragma unroll
                for (int nt = 0; nt < 4; nt++)
                    mma16816(acc[mt][nt], ah[mt], bh[nt]);
            #pragma unroll
            for (int mt = 0; mt < 4; mt++)
                #pragma unroll
                for (int nt = 0; nt < 4; nt++)
                    mma16816(acc[mt][nt], ah[mt], bl[nt]);
            #pragma unroll
            for (int mt = 0; mt < 4; mt++)
                #pragma unroll
                for (int nt = 0; nt < 4; nt++)
                    mma16816(acc[mt][nt], alr[mt], bh[nt]);
        }
    }

    const int qr = lane >> 2, qc = (lane & 3) * 2;
    #pragma unroll
    for (int mt = 0; mt < 4; mt++) {
        #pragma unroll
        for (int hrow = 0; hrow < 2; hrow++) {
            int grow = m0 + wm + mt * 16 + qr + hrow * 8;
            #pragma unroll
            for (int nt = 0; nt < 4; nt++) {
                int gcol = n0 + wn + nt * 8 + qc;
                float v0 = acc[mt][nt][hrow * 2 + 0] * alpha;
                float v1 = acc[mt][nt][hrow * 2 + 1] * alpha;
                size_t off = cbase + (size_t)grow * ldc + gcol;
                if (EPI == 4) {
                    __nv_bfloat16 bh0, bl0, bh1, bl1;
                    split2(v0, bh0, bl0); split2(v1, bh1, bl1);
                    __nv_bfloat162 ph; ph.x = bh0; ph.y = bh1;
                    __nv_bfloat162 pl; pl.x = bl0; pl.y = bl1;
                    *reinterpret_cast<__nv_bfloat162*>(Ch + off) = ph;
                    *reinterpret_cast<__nv_bfloat162*>(Cl + off) = pl;
                } else {
                    float2 o; o.x = v0; o.y = v1;
                    *reinterpret_cast<float2*>(C + off) = o;
                }
            }
        }
    }
}

// ---------------- transpose V+T head blocks (merged): sel=0 -> V, sel=1 -> T ----------------
__global__ void trans_vt2(const __nv_bfloat16* __restrict__ srch, const __nv_bfloat16* __restrict__ srcl,
                          __nv_bfloat16* __restrict__ vdh, __nv_bfloat16* __restrict__ vdl,
                          __nv_bfloat16* __restrict__ tdh, __nv_bfloat16* __restrict__ tdl) {
    __shared__ __nv_bfloat16 sh[32][34];
    __shared__ __nv_bfloat16 sl[32][34];
    int zz = blockIdx.z;
    int sel = zz >= BNB * H;
    int z = zz - sel * BNB * H;
    int bn = z >> 2, hh = z & 3;
    int coloff = 2 * CC + sel * CC;
    __nv_bfloat16* dsth = sel ? tdh : vdh;
    __nv_bfloat16* dstl = sel ? tdl : vdl;
    int d0 = blockIdx.x * 32, t0 = blockIdx.y * 32;
    int tx = threadIdx.x, ty = threadIdx.y;
    #pragma unroll
    for (int i = 0; i < 4; i++) {
        int t = t0 + ty + i * 8;
        size_t src = ((size_t)(bn * T + t)) * 2048 + coloff + hh * 128 + d0 + tx;
        sh[ty + i * 8][tx] = srch[src];
        sl[ty + i * 8][tx] = srcl[src];
    }
    __syncthreads();
    #pragma unroll
    for (int i = 0; i < 4; i++) {
        int d = d0 + ty + i * 8;
        size_t dst = ((size_t)z * DH + d) * T + t0 + tx;
        dsth[dst] = sh[tx][ty + i * 8];
        dstl[dst] = sl[tx][ty + i * 8];
    }
}

// ---------------- small prep kernels ----------------
__global__ void pad_k(const float* __restrict__ x, __nv_bfloat16* __restrict__ xph,
                      __nv_bfloat16* __restrict__ xpl) {
    size_t total = (size_t)BNB * (T + 2) * D;
    for (size_t idx = (size_t)blockIdx.x * blockDim.x + threadIdx.x; idx < total;
         idx += (size_t)gridDim.x * blockDim.x) {
        size_t bn = idx / ((T + 2) * D);
        size_t rr = idx - bn * (T + 2) * D;
        int tt = (int)(rr >> 10);
        int i = (int)(rr & 1023);
        float v = (tt == 0 || tt == T + 1) ? 0.f : x[(bn * T + (tt - 1)) * D + i];
        __nv_bfloat16 bh, bl;
        split2(v, bh, bl);
        xph[idx] = bh; xpl[idx] = bl;
    }
}

__global__ void csplit_k(const float* __restrict__ W, __nv_bfloat16* __restrict__ oh,
                         __nv_bfloat16* __restrict__ ol) {
    int total = CC * 3 * D;
    for (int idx = blockIdx.x * blockDim.x + threadIdx.x; idx < total; idx += gridDim.x * blockDim.x) {
        int c = idx / (3 * D), j = idx % (3 * D);
        int kk = j >> 10, i = j & 1023;
        float v = W[(size_t)c * 3 * D + i * 3 + kk];
        __nv_bfloat16 bh, bl; split2(v, bh, bl);
        oh[idx] = bh; ol[idx] = bl;
    }
}

__global__ void wsplit_k(const float* __restrict__ W, int N, int K,
                         __nv_bfloat16* __restrict__ oh, __nv_bfloat16* __restrict__ ol) {
    int total = N * K;
    for (int idx = blockIdx.x * blockDim.x + threadIdx.x; idx < total; idx += gridDim.x * blockDim.x) {
        int n = idx / K, k = idx % K;
        float v = W[(size_t)k * N + n];
        __nv_bfloat16 bh, bl; split2(v, bh, bl);
        oh[idx] = bh; ol[idx] = bl;
    }
}

__global__ void a2_sum_k(float* __restrict__ srow) {
    int j = threadIdx.x;
    float s = 0.f;
    for (int k = 0; k < T; k++)
        s += expf(-fabsf((float)(j - k)) / 2.718281828459045f);
    srow[j] = s;
}
__global__ void a2_fill_k(const float* __restrict__ srow, __nv_bfloat16* __restrict__ a2h,
                          __nv_bfloat16* __restrict__ a2l) {
    int i = blockIdx.x, j = threadIdx.x;
    float v = expf(-fabsf((float)(i - j)) / 2.718281828459045f) / srow[j];
    __nv_bfloat16 bh, bl; split2(v, bh, bl);
    a2h[i * T + j] = bh; a2l[i * T + j] = bl;
}
__global__ void tr1_k(const float* __restrict__ W, float* __restrict__ Wt) {
    int idx = blockIdx.x * blockDim.x + threadIdx.x;
    if (idx < CC * 32) { int c = idx / 32, o = idx % 32; Wt[idx] = W[o * CC + c]; }
}
__global__ void tr2_k(const float* __restrict__ W, float* __restrict__ Wt) {
    int idx = blockIdx.x * blockDim.x + threadIdx.x;
    if (idx < 32 * 16) { int c = idx / 16, o = idx % 16; Wt[idx] = W[o * 32 + c]; }
}

// ---------------- LayerNorm (row of 512) -> split bf16 out ----------------
__global__ void ln_k(const float* __restrict__ X, __nv_bfloat16* __restrict__ Yh,
                     __nv_bfloat16* __restrict__ Yl,
                     const float* __restrict__ g, const float* __restrict__ b) {
    int row = blockIdx.x;
    const float* x = X + (size_t)row * CC;
    int t = threadIdx.x;
    float v0 = x[t], v1 = x[t + 256];
    __shared__ float red[256];
    red[t] = v0 + v1;
    __syncthreads();
    for (int s = 128; s > 0; s >>= 1) { if (t < s) red[t] += red[t + s]; __syncthreads(); }
    float mean = red[0] * (1.f / CC);
    __syncthreads();
    float d0 = v0 - mean, d1 = v1 - mean;
    red[t] = d0 * d0 + d1 * d1;
    __syncthreads();
    for (int s = 128; s > 0; s >>= 1) { if (t < s) red[t] += red[t + s]; __syncthreads(); }
    float rstd = rsqrtf(red[0] * (1.f / CC) + EPS);
    size_t base = (size_t)row * CC;
    float y0 = d0 * rstd * g[t] + b[t];
    float y1 = d1 * rstd * g[t + 256] + b[t + 256];
    __nv_bfloat16 bh, bl;
    split2(y0, bh, bl); Yh[base + t] = bh; Yl[base + t] = bl;
    split2(y1, bh, bl); Yh[base + t + 256] = bh; Yl[base + t + 256] = bl;
}

// ---------------- softmax over rows of 256, split bf16 out ----------------
__global__ void softmax_k(const float* __restrict__ S, __nv_bfloat16* __restrict__ Sh,
                          __nv_bfloat16* __restrict__ Sl) {
    size_t row = blockIdx.x;
    const float* p = S + row * T;
    int t = threadIdx.x;
    float v = p[t];
    __shared__ float red[256];
    red[t] = v;
    __syncthreads();
    for (int s = 128; s > 0; s >>= 1) { if (t < s) red[t] = fmaxf(red[t], red[t + s]); __syncthreads(); }
    float mx = red[0];
    __syncthreads();
    float e = expf(v - mx);
    red[t] = e;
    __syncthreads();
    for (int s = 128; s > 0; s >>= 1) { if (t < s) red[t] += red[t + s]; __syncthreads(); }
    float o = e / red[0];
    __nv_bfloat16 bh, bl; split2(o, bh, bl);
    Sh[row * T + t] = bh; Sl[row * T + t] = bl;
}

// ---------------- fused head ----------------
__global__ void head_k(const float* __restrict__ Hh,
                       const float* __restrict__ W1t, const float* __restrict__ c1_b,
                       const float* __restrict__ bn1_g, const float* __restrict__ bn1_b,
                       const float* __restrict__ bn1_m, const float* __restrict__ bn1_v,
                       const float* __restrict__ W2t, const float* __restrict__ c2_b,
                       const float* __restrict__ bn2_g, const float* __restrict__ bn2_b,
                       const float* __restrict__ bn2_m, const float* __restrict__ bn2_v,
                       const float* __restrict__ c3_W, const float* __restrict__ c3_b,
                       float* __restrict__ score, float* __restrict__ dist) {
    int warp = threadIdx.x >> 5, lane = threadIdx.x & 31;
    size_t row = (size_t)blockIdx.x * 8 + warp;
    __shared__ float hs[8][CC];
    for (int idx = threadIdx.x; idx < 8 * CC; idx += 256) {
        int r = idx >> 9, c = idx & (CC - 1);
        hs[r][c] = Hh[((size_t)blockIdx.x * 8 + r) * CC + c];
    }
    __syncthreads();
    int o = lane;
    float x1 = c1_b[o];
    #pragma unroll 8
    for (int c = 0; c < CC; c++)
        x1 = fmaf(hs[warp][c], W1t[c * 32 + o], x1);
    float dd = x1 - bn1_m[o];
    float d1 = dd * dd / bn1_v[o];
    #pragma unroll
    for (int s = 16; s; s >>= 1) d1 += __shfl_xor_sync(0xffffffffu, d1, s);
    float y1 = fmaxf((x1 - bn1_m[o]) * rsqrtf(bn1_v[o] + EPS) * bn1_g[o] + bn1_b[o], 0.f);
    float x2 = (lane < 16) ? c2_b[lane] : 0.f;
    #pragma unroll
    for (int c = 0; c < 32; c++) {
        float yc = __shfl_sync(0xffffffffu, y1, c);
        if (lane < 16) x2 = fmaf(yc, W2t[c * 16 + lane], x2);
    }
    float d2 = 0.f;
    if (lane < 16) { float e = x2 - bn2_m[lane]; d2 = e * e / bn2_v[lane]; }
    #pragma unroll
    for (int s = 16; s; s >>= 1) d2 += __shfl_xor_sync(0xffffffffu, d2, s);
    float y2 = 0.f;
    if (lane < 16)
        y2 = fmaxf((x2 - bn2_m[lane]) * rsqrtf(bn2_v[lane] + EPS) * bn2_g[lane] + bn2_b[lane], 0.f);
    float sacc = (lane < 16) ? y2 * c3_W[lane] : 0.f;
    #pragma unroll
    for (int s = 16; s; s >>= 1) sacc += __shfl_xor_sync(0xffffffffu, sacc, s);
    if (lane == 0) {
        score[row] = 1.f / (1.f + expf(-(sacc + c3_b[0])));
        dist[row] = sqrtf(d1) + sqrtf(d2);
    }
}

__global__ void final_k(const float* __restrict__ dist, const float* __restrict__ score,
                        float* __restrict__ out) {
    int idx = blockIdx.x * blockDim.x + threadIdx.x;
    if (idx >= BATCH * T) return;
    int b = idx / T, t = idx % T;
    float sd = 0.f, ss = 0.f;
    for (int n = 0; n < NCROP; n++) {
        size_t r = ((size_t)(b * NCROP + n)) * T + t;
        sd += dist[r];
        ss += score[r];
    }
    out[idx] = (sd * 0.1f) * (ss * 0.1f);
}

// ---------------- host launch ----------------
template<typename P>
static P symaddr_t(const void* sym) {
    void* p = nullptr;
    cudaGetSymbolAddress(&p, sym);
    return (P)p;
}

extern "C" void kernel_launch(void* const* d_in, const int* in_sizes, int n_in,
                              void* d_out, int out_size) {
    const float* x     = (const float*)d_in[0];
    const float* W_emb = (const float*)d_in[1];
    const float* b_emb = (const float*)d_in[2];
    const float* ln1_g = (const float*)d_in[3];
    const float* ln1_b = (const float*)d_in[4];
    const float* W_qkv = (const float*)d_in[5];
    const float* W_o   = (const float*)d_in[6];
    const float* b_o   = (const float*)d_in[7];
    const float* ln2_g = (const float*)d_in[8];
    const float* ln2_b = (const float*)d_in[9];
    const float* W_f1  = (const float*)d_in[10];
    const float* b_f1  = (const float*)d_in[11];
    const float* W_f2  = (const float*)d_in[12];
    const float* b_f2  = (const float*)d_in[13];
    const float* c1_W  = (const float*)d_in[14];
    const float* c1_b  = (const float*)d_in[15];
    const float* bn1_g = (const float*)d_in[16];
    const float* bn1_b = (const float*)d_in[17];
    const float* bn1_m = (const float*)d_in[18];
    const float* bn1_v = (const float*)d_in[19];
    const float* c2_W  = (const float*)d_in[20];
    const float* c2_b  = (const float*)d_in[21];
    const float* bn2_g = (const float*)d_in[22];
    const float* bn2_b = (const float*)d_in[23];
    const float* bn2_m = (const float*)d_in[24];
    const float* bn2_v = (const float*)d_in[25];
    const float* c3_W  = (const float*)d_in[26];
    const float* c3_b  = (const float*)d_in[27];
    float* out = (float*)d_out;

    __nv_bfloat16* xph = symaddr_t<__nv_bfloat16*>(g_xph);
    __nv_bfloat16* xpl = symaddr_t<__nv_bfloat16*>(g_xpl);
    __nv_bfloat16* bteh = symaddr_t<__nv_bfloat16*>(g_bteh);
    __nv_bfloat16* btel = symaddr_t<__nv_bfloat16*>(g_btel);
    __nv_bfloat16* zh = symaddr_t<__nv_bfloat16*>(g_zh);
    __nv_bfloat16* zl = symaddr_t<__nv_bfloat16*>(g_zl);
    __nv_bfloat16* f1h = symaddr_t<__nv_bfloat16*>(g_f1h);
    __nv_bfloat16* f1l = symaddr_t<__nv_bfloat16*>(g_f1l);
    __nv_bfloat16* Ohp = symaddr_t<__nv_bfloat16*>(g_Oh);
    __nv_bfloat16* Olp = symaddr_t<__nv_bfloat16*>(g_Ol);
    __nv_bfloat16* qkh = symaddr_t<__nv_bfloat16*>(g_qkvth);
    __nv_bfloat16* qkl = symaddr_t<__nv_bfloat16*>(g_qkvtl);
    __nv_bfloat16* Shp = symaddr_t<__nv_bfloat16*>(g_Sh);
    __nv_bfloat16* Slp = symaddr_t<__nv_bfloat16*>(g_Sl);
    __nv_bfloat16* vth = symaddr_t<__nv_bfloat16*>(g_vth);
    __nv_bfloat16* vtl = symaddr_t<__nv_bfloat16*>(g_vtl);
    __nv_bfloat16* tth = symaddr_t<__nv_bfloat16*>(g_tth);
    __nv_bfloat16* ttl = symaddr_t<__nv_bfloat16*>(g_ttl);
    __nv_bfloat16* a2h = symaddr_t<__nv_bfloat16*>(g_a2h);
    __nv_bfloat16* a2l = symaddr_t<__nv_bfloat16*>(g_a2l);
    __nv_bfloat16* wqkvh = symaddr_t<__nv_bfloat16*>(g_wqkvh);
    __nv_bfloat16* wqkvl = symaddr_t<__nv_bfloat16*>(g_wqkvl);
    __nv_bfloat16* woh = symaddr_t<__nv_bfloat16*>(g_woh);
    __nv_bfloat16* wol = symaddr_t<__nv_bfloat16*>(g_wol);
    __nv_bfloat16* wf1h = symaddr_t<__nv_bfloat16*>(g_wf1h);
    __nv_bfloat16* wf1l = symaddr_t<__nv_bfloat16*>(g_wf1l);
    __nv_bfloat16* wf2h = symaddr_t<__nv_bfloat16*>(g_wf2h);
    __nv_bfloat16* wf2l = symaddr_t<__nv_bfloat16*>(g_wf2l);
    float* h    = symaddr_t<float*>(g_h);
    float* S    = symaddr_t<float*>(g_S);
    float* arow = symaddr_t<float*>(g_arow);
    float* w1t  = symaddr_t<float*>(g_w1t);
    float* w2t  = symaddr_t<float*>(g_w2t);
    float* score = symaddr_t<float*>(g_score);
    float* dist  = symaddr_t<float*>(g_dist);

    const float scale = 0.08838834764831845f;  // 1/sqrt(128)
    cudaFuncSetAttribute(mma_gemm_big<1>, cudaFuncAttributeMaxDynamicSharedMemorySize, MMB_SMEM);
    cudaFuncSetAttribute(mma_gemm_big<2>, cudaFuncAttributeMaxDynamicSharedMemorySize, MMB_SMEM);
    cudaFuncSetAttribute(mma_gemm_big<3>, cudaFuncAttributeMaxDynamicSharedMemorySize, MMB_SMEM);
    cudaFuncSetAttribute(mma_gemm_big<4>, cudaFuncAttributeMaxDynamicSharedMemorySize, MMB_SMEM);
    cudaFuncSetAttribute(mma_gemm<0>, cudaFuncAttributeMaxDynamicSharedMemorySize, MM_SMEM);
    cudaFuncSetAttribute(mma_gemm<4>, cudaFuncAttributeMaxDynamicSharedMemorySize, MM_SMEM);

    // prep ordered so conv GEMM (big kernel) is my 4th launch (ncu capture target)
    {
        size_t total = (size_t)BNB * (T + 2) * D;
        pad_k<<<(int)((total + 255) / 256), 256>>>(x, xph, xpl);                       // 1
        csplit_k<<<(3 * D * CC + 255) / 256, 256>>>(W_emb, bteh, btel);                // 2
        wsplit_k<<<(4 * CC * CC + 255) / 256, 256>>>(W_qkv, 4 * CC, CC, wqkvh, wqkvl); // 3
        // conv-as-GEMM: M=40960, N=512, K=3072 (overlapping-window A)                 // 4 <- profiled
        mma_gemm_big<1><<<dim3(CC / 256, MALL / 128), 256, MMB_SMEM>>>(
            xph, xpl, 1024, 1, bteh, btel, 3 * D, 3 * D,
            h, nullptr, nullptr, CC, b_emb);
        wsplit_k<<<(2 * CC * CC + 255) / 256, 256>>>(W_o, CC, 2 * CC, woh, wol);
        wsplit_k<<<(CC * CC + 255) / 256, 256>>>(W_f1, CC, CC, wf1h, wf1l);
        wsplit_k<<<(CC * CC + 255) / 256, 256>>>(W_f2, CC, CC, wf2h, wf2l);
        for (int l = 1; l < LDEP; l++) {
            wsplit_k<<<(4 * CC * CC + 255) / 256, 256>>>(W_qkv + (size_t)l * CC * 4 * CC, 4 * CC, CC,
                                                         wqkvh + (size_t)l * 4 * CC * CC, wqkvl + (size_t)l * 4 * CC * CC);
            wsplit_k<<<(2 * CC * CC + 255) / 256, 256>>>(W_o + (size_t)l * 2 * CC * CC, CC, 2 * CC,
                                                         woh + (size_t)l * CC * 2 * CC, wol + (size_t)l * CC * 2 * CC);
            wsplit_k<<<(CC * CC + 255) / 256, 256>>>(W_f1 + (size_t)l * CC * CC, CC, CC,
                                                     wf1h + (size_t)l * CC * CC, wf1l + (size_t)l * CC * CC);
            wsplit_k<<<(CC * CC + 255) / 256, 256>>>(W_f2 + (size_t)l * CC * CC, CC, CC,
                                                     wf2h + (size_t)l * CC * CC, wf2l + (size_t)l * CC * CC);
        }
    }

    // fixed positional attention map (split bf16)
    a2_sum_k<<<1, 256>>>(arow);
    a2_fill_k<<<T, 256>>>(arow, a2h, a2l);

    const long long rowstr = (long long)T * 4 * CC;   // qkvt batch row stride per bn
    for (int l = 0; l < LDEP; l++) {
        ln_k<<<MALL, 256>>>(h, zh, zl, ln1_g + l * CC, ln1_b + l * CC);
        // qkvt = z @ W_qkv[l] -> split bf16 (M=40960, N=2048, K=512)
        mma_gemm_big<4><<<dim3(4 * CC / 256, MALL / 128), 256, MMB_SMEM>>>(
            zh, zl, CC, 0, wqkvh + (size_t)l * 4 * CC * CC, wqkvl + (size_t)l * 4 * CC * CC,
            CC, CC, nullptr, qkh, qkl, 4 * CC, nullptr);
        // S = scale * Q @ K^T  (batched bn x H, M=N=256, K=128); K block at col offset CC
        mma_gemm<0><<<dim3(2, 2, BNB * H), 256, MM_SMEM>>>(
            qkh, qkl, 4 * CC, qkh + CC, qkl + CC, 4 * CC, DH, scale,
            S, nullptr, nullptr, T,
            H, rowstr, DH, rowstr, DH, (long long)H * T * T, (long long)T * T);
        softmax_k<<<BNB * H * T, 256>>>(S, Shp, Slp);
        // transpose V and T head blocks to [bn,h,d,t] (merged launch)
        trans_vt2<<<dim3(DH / 32, T / 32, 2 * BNB * H), dim3(32, 8)>>>(
            qkh, qkl, vth, vtl, tth, ttl);
        // o1 = S @ V  (batched bn x H, M=256, N=128, K=256)
        mma_gemm<4><<<dim3(1, 2, BNB * H), 256, MM_SMEM>>>(
            Shp, Slp, T, vth, vtl, T, T, 1.f,
            nullptr, Ohp, Olp, 2 * CC,
            H, (long long)H * T * T, (long long)T * T,
            (long long)H * DH * T, (long long)DH * T,
            (long long)T * 2 * CC, 2 * DH);
        // o2 = a2 @ Tm
        mma_gemm<4><<<dim3(1, 2, BNB * H), 256, MM_SMEM>>>(
            a2h, a2l, T, tth, ttl, T, T, 1.f,
            nullptr, Ohp + DH, Olp + DH, 2 * CC,
            H, 0, 0,
            (long long)H * DH * T, (long long)DH * T,
            (long long)T * 2 * CC, 2 * DH);
        // h = O @ W_o[l] + b_o + h   (M=40960, N=512, K=1024)
        mma_gemm_big<2><<<dim3(CC / 256, MALL / 128), 256, MMB_SMEM>>>(
            Ohp, Olp, 2 * CC, 0, woh + (size_t)l * CC * 2 * CC, wol + (size_t)l * CC * 2 * CC,
            2 * CC, 2 * CC, h, nullptr, nullptr, CC, b_o + l * CC);
        // FF
        ln_k<<<MALL, 256>>>(h, zh, zl, ln2_g + l * CC, ln2_b + l * CC);
        mma_gemm_big<3><<<dim3(CC / 256, MALL / 128), 256, MMB_SMEM>>>(
            zh, zl, CC, 0, wf1h + (size_t)l * CC * CC, wf1l + (size_t)l * CC * CC,
            CC, CC, nullptr, f1h, f1l, CC, b_f1 + l * CC);
        mma_gemm_big<2><<<dim3(CC / 256, MALL / 128), 256, MMB_SMEM>>>(
            f1h, f1l, CC, 0, wf2h + (size_t)l * CC * CC, wf2l + (size_t)l * CC * CC,
            CC, CC, h, nullptr, nullptr, CC, b_f2 + l * CC);
    }

    // head
    tr1_k<<<(CC * 32 + 255) / 256, 256>>>(c1_W, w1t);
    tr2_k<<<2, 256>>>(c2_W, w2t);
    head_k<<<MALL / 8, 256>>>(h, w1t, c1_b, bn1_g, bn1_b, bn1_m, bn1_v,
                              w2t, c2_b, bn2_g, bn2_b, bn2_m, bn2_v,
                              c3_W, c3_b, score, dist);
    final_k<<<(BATCH * T + 255) / 256, 256>>>(dist, score, out);
}

// round 13
// speedup vs baseline: 1.5594x; 1.5594x over previous
#include <cuda_runtime.h>
#include <cuda_fp16.h>
#include <math.h>
#include <stdint.h>

// Problem constants
constexpr int BATCH = 16, NCROP = 10, BNB = 160, T = 256, D = 1024, CC = 512;
constexpr int H = 4, DH = 128, LDEP = 2;
constexpr int MALL = BNB * T;               // 40960 rows
constexpr float EPS = 1e-5f;

// ---------------- device scratch (static, no allocation) ----------------
// A-side operands: fp16 hi+lo pairs. B-side operands: single fp16.
__device__ __align__(16) __half g_xph[(size_t)BNB * (T + 2) * D];
__device__ __align__(16) __half g_xpl[(size_t)BNB * (T + 2) * D];
__device__ __align__(16) __half g_bte[CC * 3 * D];                    // conv weight (B)
__device__ __align__(16) __half g_zh[(size_t)MALL * CC];
__device__ __align__(16) __half g_zl[(size_t)MALL * CC];
__device__ __align__(16) __half g_f1h[(size_t)MALL * CC];
__device__ __align__(16) __half g_f1l[(size_t)MALL * CC];
__device__ __align__(16) __half g_Oh[(size_t)MALL * 2 * CC];
__device__ __align__(16) __half g_Ol[(size_t)MALL * 2 * CC];
__device__ __align__(16) __half g_qkvth[(size_t)MALL * 4 * CC];       // hi (also K/V/T B-source)
__device__ __align__(16) __half g_qkvtl[(size_t)MALL * 4 * CC];       // lo (Q-as-A needs it)
__device__ __align__(16) __half g_Sh[(size_t)BNB * H * T * T];
__device__ __align__(16) __half g_Sl[(size_t)BNB * H * T * T];
__device__ __align__(16) __half g_vt[(size_t)BNB * H * DH * T];       // V^T (B)
__device__ __align__(16) __half g_tt[(size_t)BNB * H * DH * T];       // T^T (B)
__device__ __align__(16) __half g_a2h[T * T];
__device__ __align__(16) __half g_a2l[T * T];
__device__ __align__(16) __half g_wqkv[LDEP * 4 * CC * CC];           // B
__device__ __align__(16) __half g_wo[LDEP * CC * 2 * CC];             // B
__device__ __align__(16) __half g_wf1[LDEP * CC * CC];                // B
__device__ __align__(16) __half g_wf2[LDEP * CC * CC];                // B
// fp32 buffers
__device__ __align__(16) float g_h[(size_t)MALL * CC];
__device__ __align__(16) float g_S[(size_t)BNB * H * T * T];
__device__ float g_arow[T];
__device__ float g_w1t[CC * 32];
__device__ float g_w2t[32 * 16];
__device__ float g_score[MALL];
__device__ float g_dist[MALL];

// ---------------- helpers ----------------
__device__ __forceinline__ void split2h(float x, __half& hi, __half& lo) {
    hi = __float2half(x);
    lo = __float2half(x - __half2float(hi));
}
__device__ __forceinline__ uint32_t smem_u32(const void* p) {
    uint32_t a;
    asm("{ .reg .u64 t; cvta.to.shared.u64 t, %1; cvt.u32.u64 %0, t; }" : "=r"(a) : "l"(p));
    return a;
}
__device__ __forceinline__ void cp16(uint32_t dst, const void* src) {
    asm volatile("cp.async.cg.shared.global [%0], [%1], 16;" :: "r"(dst), "l"(src));
}
__device__ __forceinline__ void cp_commit() {
    asm volatile("cp.async.commit_group;" ::: "memory");
}
template<int N>
__device__ __forceinline__ void cp_wait() {
    asm volatile("cp.async.wait_group %0;" :: "n"(N) : "memory");
}
__device__ __forceinline__ void ldsm4(uint32_t& r0, uint32_t& r1, uint32_t& r2, uint32_t& r3, uint32_t addr) {
    asm volatile("ldmatrix.sync.aligned.m8n8.x4.shared.b16 {%0,%1,%2,%3}, [%4];"
                 : "=r"(r0), "=r"(r1), "=r"(r2), "=r"(r3) : "r"(addr));
}
__device__ __forceinline__ void mma16816(float* c, const uint32_t* a, const uint32_t* b) {
    asm volatile(
        "mma.sync.aligned.m16n8k16.row.col.f32.f16.f16.f32 "
        "{%0,%1,%2,%3}, {%4,%5,%6,%7}, {%8,%9}, {%0,%1,%2,%3};"
        : "+f"(c[0]), "+f"(c[1]), "+f"(c[2]), "+f"(c[3])
        : "r"(a[0]), "r"(a[1]), "r"(a[2]), "r"(a[3]), "r"(b[0]), "r"(b[1]));
}

// ================= HMMA fp16 2-term GEMM: C(M,N) = alpha * (Ah+Al)(M,K) @ B(N,K)^T ============
// 128x128 CTA tile, 8 warps of 64x32, BK=32, cp.async double buffer, two-level batch.
// Term-major (all Ah*B, then all Al*B), 2 CTAs/SM.
// EPI: 0 fp32 store (alpha); 1 +bias relu fp32; 2 +bias +C fp32; 3 +bias gelu split; 4 plain split.
constexpr int LDS = 40;                      // halves per smem row (32 data + 8 pad)
constexpr int TILE_B = 128 * LDS * 2;        // 10240 bytes per tile
constexpr int STAGE_B = 3 * TILE_B;          // Ah, Al, B
constexpr int MM_SMEM = 2 * STAGE_B;         // 61440

template<int EPI>
__global__ void __launch_bounds__(256, 2) mma_gemm(
    const __half* __restrict__ Ah, const __half* __restrict__ Al,
    int lda, int convA,
    const __half* __restrict__ B,
    int ldb, int K, float alpha,
    float* __restrict__ C,
    __half* __restrict__ Ch, __half* __restrict__ Cl,
    int ldc, const float* __restrict__ bias,
    int H2, long long sA1, long long sA2, long long sB1, long long sB2,
    long long sC1, long long sC2)
{
    extern __shared__ __align__(1024) char smem[];
    const uint32_t sbase = smem_u32(smem);
    const int tid = threadIdx.x, lane = tid & 31, wid = tid >> 5;
    const int bz = blockIdx.z;
    const int b1 = bz / H2, b2 = bz - b1 * H2;
    const size_t abase = (size_t)b1 * sA1 + (size_t)b2 * sA2;
    const size_t bbase = (size_t)b1 * sB1 + (size_t)b2 * sB2;
    const size_t cbase = (size_t)b1 * sC1 + (size_t)b2 * sC2;
    const int m0 = blockIdx.y * 128, n0 = blockIdx.x * 128;
    const int wm = (wid & 1) * 64, wn = (wid >> 1) * 32;

    // ---- per-thread load plan: 6 chunks of 16B (Ah, Al, B tiles) ----
    const __half* srcp[6];
    uint32_t doff[6];
    #pragma unroll
    for (int q = 0; q < 6; q++) {
        int ci = q * 256 + tid;
        int u = ci >> 9;                 // 0:Ah 1:Al 2:B
        int r = (ci >> 2) & 127;
        int c16 = ci & 3;                // 16B chunk within 64B row
        doff[q] = (uint32_t)(u * TILE_B + r * (LDS * 2) + c16 * 16);
        if (u < 2) {
            int gr = m0 + r;
            size_t ro = abase + (size_t)gr * lda + (convA ? (size_t)(gr >> 8) * 2048 : 0) + c16 * 8;
            srcp[q] = (u == 0 ? Ah : Al) + ro;
        } else {
            size_t ro = bbase + (size_t)(n0 + r) * ldb + c16 * 8;
            srcp[q] = B + ro;
        }
    }

    const int nc = K / 32;
    #pragma unroll
    for (int q = 0; q < 6; q++) cp16(sbase + doff[q], srcp[q]);
    cp_commit();

    float acc[4][4][4] = {};
    const int lrowA = lane & 15, lkA = (lane >> 4) << 3;
    const int lrowB = ((lane >> 4) << 3) + (lane & 7), lkB = ((lane >> 3) & 1) << 3;

    for (int c = 0; c < nc; c++) {
        if (c + 1 < nc) {
            uint32_t st = sbase + (uint32_t)(((c + 1) & 1) * STAGE_B);
            int k0 = (c + 1) * 32;
            #pragma unroll
            for (int q = 0; q < 6; q++) cp16(st + doff[q], srcp[q] + k0);
            cp_commit();
            cp_wait<1>();
        } else {
            cp_wait<0>();
        }
        __syncthreads();

        uint32_t sa = sbase + (uint32_t)((c & 1) * STAGE_B);
        #pragma unroll
        for (int kk2 = 0; kk2 < 2; kk2++) {
            const int kk = kk2 * 16;
            uint32_t ah[4][4], alr[4][4], bh[4][2];
            #pragma unroll
            for (int mt = 0; mt < 4; mt++) {
                uint32_t ra = sa + (uint32_t)((wm + mt * 16 + lrowA) * (LDS * 2) + (kk + lkA) * 2);
                ldsm4(ah[mt][0], ah[mt][1], ah[mt][2], ah[mt][3], ra);
                ldsm4(alr[mt][0], alr[mt][1], alr[mt][2], alr[mt][3], ra + TILE_B);
            }
            #pragma unroll
            for (int np = 0; np < 2; np++) {
                uint32_t rb = sa + (uint32_t)(2 * TILE_B + (wn + np * 16 + lrowB) * (LDS * 2) + (kk + lkB) * 2);
                uint32_t h0, h1, h2, h3;
                ldsm4(h0, h1, h2, h3, rb);
                bh[np * 2][0] = h0; bh[np * 2][1] = h1;
                bh[np * 2 + 1][0] = h2; bh[np * 2 + 1][1] = h3;
            }
            // term-major: all Ah*B, then all Al*B — 16 independent MMAs between acc reuse.
            #pragma unroll
            for (int mt = 0; mt < 4; mt++)
                #pragma unroll
                for (int nt = 0; nt < 4; nt++)
                    mma16816(acc[mt][nt], ah[mt], bh[nt]);
            #pragma unroll
            for (int mt = 0; mt < 4; mt++)
                #pragma unroll
                for (int nt = 0; nt < 4; nt++)
                    mma16816(acc[mt][nt], alr[mt], bh[nt]);
        }
        __syncthreads();
    }

    // ---- epilogue ----
    const int qr = lane >> 2, qc = (lane & 3) * 2;
    #pragma unroll
    for (int mt = 0; mt < 4; mt++) {
        #pragma unroll
        for (int hrow = 0; hrow < 2; hrow++) {
            int grow = m0 + wm + mt * 16 + qr + hrow * 8;
            #pragma unroll
            for (int nt = 0; nt < 4; nt++) {
                int gcol = n0 + wn + nt * 8 + qc;
                float v0 = acc[mt][nt][hrow * 2 + 0] * alpha;
                float v1 = acc[mt][nt][hrow * 2 + 1] * alpha;
                if (EPI == 1 || EPI == 2 || EPI == 3) { v0 += bias[gcol]; v1 += bias[gcol + 1]; }
                if (EPI == 1) { v0 = fmaxf(v0, 0.f); v1 = fmaxf(v1, 0.f); }
                if (EPI == 3) {
                    v0 = 0.5f * v0 * (1.f + erff(v0 * 0.70710678118654752f));
                    v1 = 0.5f * v1 * (1.f + erff(v1 * 0.70710678118654752f));
                }
                size_t off = cbase + (size_t)grow * ldc + gcol;
                if (EPI == 3 || EPI == 4) {
                    __half h0, l0, h1, l1;
                    split2h(v0, h0, l0); split2h(v1, h1, l1);
                    __half2 ph; ph.x = h0; ph.y = h1;
                    __half2 pl; pl.x = l0; pl.y = l1;
                    *reinterpret_cast<__half2*>(Ch + off) = ph;
                    *reinterpret_cast<__half2*>(Cl + off) = pl;
                } else {
                    if (EPI == 2) {
                        float2 old = *reinterpret_cast<const float2*>(C + off);
                        v0 += old.x; v1 += old.y;
                    }
                    float2 o; o.x = v0; o.y = v1;
                    *reinterpret_cast<float2*>(C + off) = o;
                }
            }
        }
    }
}

// ---------------- transpose V+T head blocks (hi only; B operands): sel=0 -> V, sel=1 -> T ---
__global__ void trans_vt2(const __half* __restrict__ srch,
                          __half* __restrict__ vd, __half* __restrict__ td) {
    __shared__ __half sh[32][34];
    int zz = blockIdx.z;
    int sel = zz >= BNB * H;
    int z = zz - sel * BNB * H;
    int bn = z >> 2, hh = z & 3;
    int coloff = 2 * CC + sel * CC;
    __half* dst = sel ? td : vd;
    int d0 = blockIdx.x * 32, t0 = blockIdx.y * 32;
    int tx = threadIdx.x, ty = threadIdx.y;
    #pragma unroll
    for (int i = 0; i < 4; i++) {
        int t = t0 + ty + i * 8;
        size_t src = ((size_t)(bn * T + t)) * 2048 + coloff + hh * 128 + d0 + tx;
        sh[ty + i * 8][tx] = srch[src];
    }
    __syncthreads();
    #pragma unroll
    for (int i = 0; i < 4; i++) {
        int d = d0 + ty + i * 8;
        size_t dst_i = ((size_t)z * DH + d) * T + t0 + tx;
        dst[dst_i] = sh[tx][ty + i * 8];
    }
}

// ---------------- small prep kernels ----------------
__global__ void pad_k(const float* __restrict__ x, __half* __restrict__ xph,
                      __half* __restrict__ xpl) {
    size_t total = (size_t)BNB * (T + 2) * D;
    for (size_t idx = (size_t)blockIdx.x * blockDim.x + threadIdx.x; idx < total;
         idx += (size_t)gridDim.x * blockDim.x) {
        size_t bn = idx / ((T + 2) * D);
        size_t rr = idx - bn * (T + 2) * D;
        int tt = (int)(rr >> 10);
        int i = (int)(rr & 1023);
        float v = (tt == 0 || tt == T + 1) ? 0.f : x[(bn * T + (tt - 1)) * D + i];
        __half bh, bl;
        split2h(v, bh, bl);
        xph[idx] = bh; xpl[idx] = bl;
    }
}

__global__ void csplit_k(const float* __restrict__ W, __half* __restrict__ o) {
    int total = CC * 3 * D;
    for (int idx = blockIdx.x * blockDim.x + threadIdx.x; idx < total; idx += gridDim.x * blockDim.x) {
        int c = idx / (3 * D), j = idx % (3 * D);
        int kk = j >> 10, i = j & 1023;
        o[idx] = __float2half(W[(size_t)c * 3 * D + i * 3 + kk]);
    }
}

__global__ void wsplit_k(const float* __restrict__ W, int N, int K, __half* __restrict__ o) {
    int total = N * K;
    for (int idx = blockIdx.x * blockDim.x + threadIdx.x; idx < total; idx += gridDim.x * blockDim.x) {
        int n = idx / K, k = idx % K;
        o[idx] = __float2half(W[(size_t)k * N + n]);
    }
}

__global__ void a2_sum_k(float* __restrict__ srow) {
    int j = threadIdx.x;
    float s = 0.f;
    for (int k = 0; k < T; k++)
        s += expf(-fabsf((float)(j - k)) / 2.718281828459045f);
    srow[j] = s;
}
__global__ void a2_fill_k(const float* __restrict__ srow, __half* __restrict__ a2h,
                          __half* __restrict__ a2l) {
    int i = blockIdx.x, j = threadIdx.x;
    float v = expf(-fabsf((float)(i - j)) / 2.718281828459045f) / srow[j];
    __half bh, bl; split2h(v, bh, bl);
    a2h[i * T + j] = bh; a2l[i * T + j] = bl;
}
__global__ void tr1_k(const float* __restrict__ W, float* __restrict__ Wt) {
    int idx = blockIdx.x * blockDim.x + threadIdx.x;
    if (idx < CC * 32) { int c = idx / 32, o = idx % 32; Wt[idx] = W[o * CC + c]; }
}
__global__ void tr2_k(const float* __restrict__ W, float* __restrict__ Wt) {
    int idx = blockIdx.x * blockDim.x + threadIdx.x;
    if (idx < 32 * 16) { int c = idx / 16, o = idx % 16; Wt[idx] = W[o * 32 + c]; }
}

// ---------------- LayerNorm (row of 512) -> split fp16 out ----------------
__global__ void ln_k(const float* __restrict__ X, __half* __restrict__ Yh,
                     __half* __restrict__ Yl,
                     const float* __restrict__ g, const float* __restrict__ b) {
    int row = blockIdx.x;
    const float* x = X + (size_t)row * CC;
    int t = threadIdx.x;
    float v0 = x[t], v1 = x[t + 256];
    __shared__ float red[256];
    red[t] = v0 + v1;
    __syncthreads();
    for (int s = 128; s > 0; s >>= 1) { if (t < s) red[t] += red[t + s]; __syncthreads(); }
    float mean = red[0] * (1.f / CC);
    __syncthreads();
    float d0 = v0 - mean, d1 = v1 - mean;
    red[t] = d0 * d0 + d1 * d1;
    __syncthreads();
    for (int s = 128; s > 0; s >>= 1) { if (t < s) red[t] += red[t + s]; __syncthreads(); }
    float rstd = rsqrtf(red[0] * (1.f / CC) + EPS);
    size_t base = (size_t)row * CC;
    float y0 = d0 * rstd * g[t] + b[t];
    float y1 = d1 * rstd * g[t + 256] + b[t + 256];
    __half bh, bl;
    split2h(y0, bh, bl); Yh[base + t] = bh; Yl[base + t] = bl;
    split2h(y1, bh, bl); Yh[base + t + 256] = bh; Yl[base + t + 256] = bl;
}

// ---------------- softmax over rows of 256, split fp16 out ----------------
__global__ void softmax_k(const float* __restrict__ S, __half* __restrict__ Sh,
                          __half* __restrict__ Sl) {
    size_t row = blockIdx.x;
    const float* p = S + row * T;
    int t = threadIdx.x;
    float v = p[t];
    __shared__ float red[256];
    red[t] = v;
    __syncthreads();
    for (int s = 128; s > 0; s >>= 1) { if (t < s) red[t] = fmaxf(red[t], red[t + s]); __syncthreads(); }
    float mx = red[0];
    __syncthreads();
    float e = expf(v - mx);
    red[t] = e;
    __syncthreads();
    for (int s = 128; s > 0; s >>= 1) { if (t < s) red[t] += red[t + s]; __syncthreads(); }
    float o = e / red[0];
    __half bh, bl; split2h(o, bh, bl);
    Sh[row * T + t] = bh; Sl[row * T + t] = bl;
}

// ---------------- fused head ----------------
__global__ void head_k(const float* __restrict__ Hh,
                       const float* __restrict__ W1t, const float* __restrict__ c1_b,
                       const float* __restrict__ bn1_g, const float* __restrict__ bn1_b,
                       const float* __restrict__ bn1_m, const float* __restrict__ bn1_v,
                       const float* __restrict__ W2t, const float* __restrict__ c2_b,
                       const float* __restrict__ bn2_g, const float* __restrict__ bn2_b,
                       const float* __restrict__ bn2_m, const float* __restrict__ bn2_v,
                       const float* __restrict__ c3_W, const float* __restrict__ c3_b,
                       float* __restrict__ score, float* __restrict__ dist) {
    int warp = threadIdx.x >> 5, lane = threadIdx.x & 31;
    size_t row = (size_t)blockIdx.x * 8 + warp;
    __shared__ float hs[8][CC];
    for (int idx = threadIdx.x; idx < 8 * CC; idx += 256) {
        int r = idx >> 9, c = idx & (CC - 1);
        hs[r][c] = Hh[((size_t)blockIdx.x * 8 + r) * CC + c];
    }
    __syncthreads();
    int o = lane;
    float x1 = c1_b[o];
    #pragma unroll 8
    for (int c = 0; c < CC; c++)
        x1 = fmaf(hs[warp][c], W1t[c * 32 + o], x1);
    float dd = x1 - bn1_m[o];
    float d1 = dd * dd / bn1_v[o];
    #pragma unroll
    for (int s = 16; s; s >>= 1) d1 += __shfl_xor_sync(0xffffffffu, d1, s);
    float y1 = fmaxf((x1 - bn1_m[o]) * rsqrtf(bn1_v[o] + EPS) * bn1_g[o] + bn1_b[o], 0.f);
    float x2 = (lane < 16) ? c2_b[lane] : 0.f;
    #pragma unroll
    for (int c = 0; c < 32; c++) {
        float yc = __shfl_sync(0xffffffffu, y1, c);
        if (lane < 16) x2 = fmaf(yc, W2t[c * 16 + lane], x2);
    }
    float d2 = 0.f;
    if (lane < 16) { float e = x2 - bn2_m[lane]; d2 = e * e / bn2_v[lane]; }
    #pragma unroll
    for (int s = 16; s; s >>= 1) d2 += __shfl_xor_sync(0xffffffffu, d2, s);
    float y2 = 0.f;
    if (lane < 16)
        y2 = fmaxf((x2 - bn2_m[lane]) * rsqrtf(bn2_v[lane] + EPS) * bn2_g[lane] + bn2_b[lane], 0.f);
    float sacc = (lane < 16) ? y2 * c3_W[lane] : 0.f;
    #pragma unroll
    for (int s = 16; s; s >>= 1) sacc += __shfl_xor_sync(0xffffffffu, sacc, s);
    if (lane == 0) {
        score[row] = 1.f / (1.f + expf(-(sacc + c3_b[0])));
        dist[row] = sqrtf(d1) + sqrtf(d2);
    }
}

__global__ void final_k(const float* __restrict__ dist, const float* __restrict__ score,
                        float* __restrict__ out) {
    int idx = blockIdx.x * blockDim.x + threadIdx.x;
    if (idx >= BATCH * T) return;
    int b = idx / T, t = idx % T;
    float sd = 0.f, ss = 0.f;
    for (int n = 0; n < NCROP; n++) {
        size_t r = ((size_t)(b * NCROP + n)) * T + t;
        sd += dist[r];
        ss += score[r];
    }
    out[idx] = (sd * 0.1f) * (ss * 0.1f);
}

// ---------------- host launch ----------------
template<typename P>
static P symaddr_t(const void* sym) {
    void* p = nullptr;
    cudaGetSymbolAddress(&p, sym);
    return (P)p;
}

extern "C" void kernel_launch(void* const* d_in, const int* in_sizes, int n_in,
                              void* d_out, int out_size) {
    const float* x     = (const float*)d_in[0];
    const float* W_emb = (const float*)d_in[1];
    const float* b_emb = (const float*)d_in[2];
    const float* ln1_g = (const float*)d_in[3];
    const float* ln1_b = (const float*)d_in[4];
    const float* W_qkv = (const float*)d_in[5];
    const float* W_o   = (const float*)d_in[6];
    const float* b_o   = (const float*)d_in[7];
    const float* ln2_g = (const float*)d_in[8];
    const float* ln2_b = (const float*)d_in[9];
    const float* W_f1  = (const float*)d_in[10];
    const float* b_f1  = (const float*)d_in[11];
    const float* W_f2  = (const float*)d_in[12];
    const float* b_f2  = (const float*)d_in[13];
    const float* c1_W  = (const float*)d_in[14];
    const float* c1_b  = (const float*)d_in[15];
    const float* bn1_g = (const float*)d_in[16];
    const float* bn1_b = (const float*)d_in[17];
    const float* bn1_m = (const float*)d_in[18];
    const float* bn1_v = (const float*)d_in[19];
    const float* c2_W  = (const float*)d_in[20];
    const float* c2_b  = (const float*)d_in[21];
    const float* bn2_g = (const float*)d_in[22];
    const float* bn2_b = (const float*)d_in[23];
    const float* bn2_m = (const float*)d_in[24];
    const float* bn2_v = (const float*)d_in[25];
    const float* c3_W  = (const float*)d_in[26];
    const float* c3_b  = (const float*)d_in[27];
    float* out = (float*)d_out;

    __half* xph = symaddr_t<__half*>(g_xph);
    __half* xpl = symaddr_t<__half*>(g_xpl);
    __half* bte = symaddr_t<__half*>(g_bte);
    __half* zh = symaddr_t<__half*>(g_zh);
    __half* zl = symaddr_t<__half*>(g_zl);
    __half* f1h = symaddr_t<__half*>(g_f1h);
    __half* f1l = symaddr_t<__half*>(g_f1l);
    __half* Ohp = symaddr_t<__half*>(g_Oh);
    __half* Olp = symaddr_t<__half*>(g_Ol);
    __half* qkh = symaddr_t<__half*>(g_qkvth);
    __half* qkl = symaddr_t<__half*>(g_qkvtl);
    __half* Shp = symaddr_t<__half*>(g_Sh);
    __half* Slp = symaddr_t<__half*>(g_Sl);
    __half* vt = symaddr_t<__half*>(g_vt);
    __half* tt = symaddr_t<__half*>(g_tt);
    __half* a2h = symaddr_t<__half*>(g_a2h);
    __half* a2l = symaddr_t<__half*>(g_a2l);
    __half* wqkv = symaddr_t<__half*>(g_wqkv);
    __half* wo = symaddr_t<__half*>(g_wo);
    __half* wf1 = symaddr_t<__half*>(g_wf1);
    __half* wf2 = symaddr_t<__half*>(g_wf2);
    float* h    = symaddr_t<float*>(g_h);
    float* S    = symaddr_t<float*>(g_S);
    float* arow = symaddr_t<float*>(g_arow);
    float* w1t  = symaddr_t<float*>(g_w1t);
    float* w2t  = symaddr_t<float*>(g_w2t);
    float* score = symaddr_t<float*>(g_score);
    float* dist  = symaddr_t<float*>(g_dist);

    const float scale = 0.08838834764831845f;  // 1/sqrt(128)
    cudaFuncSetAttribute(mma_gemm<0>, cudaFuncAttributeMaxDynamicSharedMemorySize, MM_SMEM);
    cudaFuncSetAttribute(mma_gemm<1>, cudaFuncAttributeMaxDynamicSharedMemorySize, MM_SMEM);
    cudaFuncSetAttribute(mma_gemm<2>, cudaFuncAttributeMaxDynamicSharedMemorySize, MM_SMEM);
    cudaFuncSetAttribute(mma_gemm<3>, cudaFuncAttributeMaxDynamicSharedMemorySize, MM_SMEM);
    cudaFuncSetAttribute(mma_gemm<4>, cudaFuncAttributeMaxDynamicSharedMemorySize, MM_SMEM);

    // prep ordered so conv GEMM is my 4th launch (ncu capture target)
    {
        size_t total = (size_t)BNB * (T + 2) * D;
        pad_k<<<(int)((total + 255) / 256), 256>>>(x, xph, xpl);                       // 1
        csplit_k<<<(3 * D * CC + 255) / 256, 256>>>(W_emb, bte);                       // 2
        wsplit_k<<<(4 * CC * CC + 255) / 256, 256>>>(W_qkv, 4 * CC, CC, wqkv);         // 3
        // conv-as-GEMM: M=40960, N=512, K=3072 (overlapping-window A)                 // 4 <- profiled
        mma_gemm<1><<<dim3(CC / 128, MALL / 128), 256, MM_SMEM>>>(
            xph, xpl, 1024, 1, bte, 3 * D, 3 * D, 1.f,
            h, nullptr, nullptr, CC, b_emb, 1, 0, 0, 0, 0, 0, 0);
        wsplit_k<<<(2 * CC * CC + 255) / 256, 256>>>(W_o, CC, 2 * CC, wo);
        wsplit_k<<<(CC * CC + 255) / 256, 256>>>(W_f1, CC, CC, wf1);
        wsplit_k<<<(CC * CC + 255) / 256, 256>>>(W_f2, CC, CC, wf2);
        for (int l = 1; l < LDEP; l++) {
            wsplit_k<<<(4 * CC * CC + 255) / 256, 256>>>(W_qkv + (size_t)l * CC * 4 * CC, 4 * CC, CC,
                                                         wqkv + (size_t)l * 4 * CC * CC);
            wsplit_k<<<(2 * CC * CC + 255) / 256, 256>>>(W_o + (size_t)l * 2 * CC * CC, CC, 2 * CC,
                                                         wo + (size_t)l * CC * 2 * CC);
            wsplit_k<<<(CC * CC + 255) / 256, 256>>>(W_f1 + (size_t)l * CC * CC, CC, CC,
                                                     wf1 + (size_t)l * CC * CC);
            wsplit_k<<<(CC * CC + 255) / 256, 256>>>(W_f2 + (size_t)l * CC * CC, CC, CC,
                                                     wf2 + (size_t)l * CC * CC);
        }
    }

    // fixed positional attention map (split fp16)
    a2_sum_k<<<1, 256>>>(arow);
    a2_fill_k<<<T, 256>>>(arow, a2h, a2l);

    const long long rowstr = (long long)T * 4 * CC;   // qkvt batch row stride per bn
    for (int l = 0; l < LDEP; l++) {
        ln_k<<<MALL, 256>>>(h, zh, zl, ln1_g + l * CC, ln1_b + l * CC);
        // qkvt = z @ W_qkv[l] -> split fp16 (M=40960, N=2048, K=512)
        mma_gemm<4><<<dim3(4 * CC / 128, MALL / 128), 256, MM_SMEM>>>(
            zh, zl, CC, 0, wqkv + (size_t)l * 4 * CC * CC,
            CC, CC, 1.f, nullptr, qkh, qkl, 4 * CC, nullptr, 1, 0, 0, 0, 0, 0, 0);
        // S = scale * Q @ K^T  (batched bn x H, M=N=256, K=128); K block (hi) at col offset CC
        mma_gemm<0><<<dim3(2, 2, BNB * H), 256, MM_SMEM>>>(
            qkh, qkl, 4 * CC, 0, qkh + CC, 4 * CC, DH, scale,
            S, nullptr, nullptr, T, nullptr,
            H, rowstr, DH, rowstr, DH, (long long)H * T * T, (long long)T * T);
        softmax_k<<<BNB * H * T, 256>>>(S, Shp, Slp);
        // transpose V and T head blocks (hi only) to [bn,h,d,t]
        trans_vt2<<<dim3(DH / 32, T / 32, 2 * BNB * H), dim3(32, 8)>>>(qkh, vt, tt);
        // o1 = S @ V  (batched bn x H, M=256, N=128, K=256)
        mma_gemm<4><<<dim3(1, 2, BNB * H), 256, MM_SMEM>>>(
            Shp, Slp, T, 0, vt, T, T, 1.f,
            nullptr, Ohp, Olp, 2 * CC, nullptr,
            H, (long long)H * T * T, (long long)T * T,
            (long long)H * DH * T, (long long)DH * T,
            (long long)T * 2 * CC, 2 * DH);
        // o2 = a2 @ Tm
        mma_gemm<4><<<dim3(1, 2, BNB * H), 256, MM_SMEM>>>(
            a2h, a2l, T, 0, tt, T, T, 1.f,
            nullptr, Ohp + DH, Olp + DH, 2 * CC, nullptr,
            H, 0, 0,
            (long long)H * DH * T, (long long)DH * T,
            (long long)T * 2 * CC, 2 * DH);
        // h = O @ W_o[l] + b_o + h   (M=40960, N=512, K=1024)
        mma_gemm<2><<<dim3(CC / 128, MALL / 128), 256, MM_SMEM>>>(
            Ohp, Olp, 2 * CC, 0, wo + (size_t)l * CC * 2 * CC,
            2 * CC, 2 * CC, 1.f, h, nullptr, nullptr, CC, b_o + l * CC, 1, 0, 0, 0, 0, 0, 0);
        // FF
        ln_k<<<MALL, 256>>>(h, zh, zl, ln2_g + l * CC, ln2_b + l * CC);
        mma_gemm<3><<<dim3(CC / 128, MALL / 128), 256, MM_SMEM>>>(
            zh, zl, CC, 0, wf1 + (size_t)l * CC * CC,
            CC, CC, 1.f, nullptr, f1h, f1l, CC, b_f1 + l * CC, 1, 0, 0, 0, 0, 0, 0);
        mma_gemm<2><<<dim3(CC / 128, MALL / 128), 256, MM_SMEM>>>(
            f1h, f1l, CC, 0, wf2 + (size_t)l * CC * CC,
            CC, CC, 1.f, h, nullptr, nullptr, CC, b_f2 + l * CC, 1, 0, 0, 0, 0, 0, 0);
    }

    // head
    tr1_k<<<(CC * 32 + 255) / 256, 256>>>(c1_W, w1t);
    tr2_k<<<2, 256>>>(c2_W, w2t);
    head_k<<<MALL / 8, 256>>>(h, w1t, c1_b, bn1_g, bn1_b, bn1_m, bn1_v,
                              w2t, c2_b, bn2_g, bn2_b, bn2_m, bn2_v,
                              c3_W, c3_b, score, dist);
    final_k<<<(BATCH * T + 255) / 256, 256>>>(dist, score, out);
}

// round 14
// speedup vs baseline: 2.2425x; 1.4381x over previous
#include <cuda_runtime.h>
#include <cuda_fp16.h>
#include <math.h>
#include <stdint.h>

// Problem constants
constexpr int BATCH = 16, NCROP = 10, BNB = 160, T = 256, D = 1024, CC = 512;
constexpr int H = 4, DH = 128, LDEP = 2;
constexpr int MALL = BNB * T;               // 40960 rows
constexpr float EPS = 1e-5f;

// ---------------- device scratch (static, no allocation) ----------------
// All GEMM operands: single fp16.
__device__ __align__(16) __half g_xp[(size_t)BNB * (T + 2) * D];
__device__ __align__(16) __half g_bte[CC * 3 * D];
__device__ __align__(16) __half g_z[(size_t)MALL * CC];
__device__ __align__(16) __half g_f1[(size_t)MALL * CC];
__device__ __align__(16) __half g_O[(size_t)MALL * 2 * CC];
__device__ __align__(16) __half g_qkvt[(size_t)MALL * 4 * CC];
__device__ __align__(16) __half g_Sh[(size_t)BNB * H * T * T];
__device__ __align__(16) __half g_vt[(size_t)BNB * H * DH * T];
__device__ __align__(16) __half g_tt[(size_t)BNB * H * DH * T];
__device__ __align__(16) __half g_a2[T * T];
__device__ __align__(16) __half g_wqkv[LDEP * 4 * CC * CC];
__device__ __align__(16) __half g_wo[LDEP * CC * 2 * CC];
__device__ __align__(16) __half g_wf1[LDEP * CC * CC];
__device__ __align__(16) __half g_wf2[LDEP * CC * CC];
// fp32 buffers
__device__ __align__(16) float g_h[(size_t)MALL * CC];
__device__ __align__(16) float g_S[(size_t)BNB * H * T * T];
__device__ float g_arow[T];
__device__ float g_w1t[CC * 32];
__device__ float g_w2t[32 * 16];
__device__ float g_score[MALL];
__device__ float g_dist[MALL];

// ---------------- helpers ----------------
__device__ __forceinline__ uint32_t smem_u32(const void* p) {
    uint32_t a;
    asm("{ .reg .u64 t; cvta.to.shared.u64 t, %1; cvt.u32.u64 %0, t; }" : "=r"(a) : "l"(p));
    return a;
}
__device__ __forceinline__ void cp16(uint32_t dst, const void* src) {
    asm volatile("cp.async.cg.shared.global [%0], [%1], 16;" :: "r"(dst), "l"(src));
}
__device__ __forceinline__ void cp_commit() {
    asm volatile("cp.async.commit_group;" ::: "memory");
}
template<int N>
__device__ __forceinline__ void cp_wait() {
    asm volatile("cp.async.wait_group %0;" :: "n"(N) : "memory");
}
__device__ __forceinline__ void ldsm4(uint32_t& r0, uint32_t& r1, uint32_t& r2, uint32_t& r3, uint32_t addr) {
    asm volatile("ldmatrix.sync.aligned.m8n8.x4.shared.b16 {%0,%1,%2,%3}, [%4];"
                 : "=r"(r0), "=r"(r1), "=r"(r2), "=r"(r3) : "r"(addr));
}
__device__ __forceinline__ void mma16816(float* c, const uint32_t* a, const uint32_t* b) {
    asm volatile(
        "mma.sync.aligned.m16n8k16.row.col.f32.f16.f16.f32 "
        "{%0,%1,%2,%3}, {%4,%5,%6,%7}, {%8,%9}, {%0,%1,%2,%3};"
        : "+f"(c[0]), "+f"(c[1]), "+f"(c[2]), "+f"(c[3])
        : "r"(a[0]), "r"(a[1]), "r"(a[2]), "r"(a[3]), "r"(b[0]), "r"(b[1]));
}

// ================= plain fp16 HMMA GEMM: C(M,N) = alpha * A(M,K) @ B(N,K)^T =================
// 128x128 CTA tile, 8 warps of 64x32, BK=32, cp.async double buffer, two-level batch, 2 CTA/SM.
// EPI: 0 fp32 store (alpha); 1 +bias relu fp32; 2 +bias +C fp32; 3 +bias gelu fp16; 4 plain fp16.
constexpr int LDS = 40;                      // halves per smem row (32 data + 8 pad)
constexpr int TILE_B = 128 * LDS * 2;        // 10240 bytes per tile
constexpr int STAGE_B = 2 * TILE_B;          // A, B
constexpr int MM_SMEM = 2 * STAGE_B;         // 40960

template<int EPI>
__global__ void __launch_bounds__(256, 2) mma_gemm(
    const __half* __restrict__ A, int lda, int convA,
    const __half* __restrict__ B, int ldb, int K, float alpha,
    float* __restrict__ C, __half* __restrict__ Ch,
    int ldc, const float* __restrict__ bias,
    int H2, long long sA1, long long sA2, long long sB1, long long sB2,
    long long sC1, long long sC2)
{
    extern __shared__ __align__(1024) char smem[];
    const uint32_t sbase = smem_u32(smem);
    const int tid = threadIdx.x, lane = tid & 31, wid = tid >> 5;
    const int bz = blockIdx.z;
    const int b1 = bz / H2, b2 = bz - b1 * H2;
    const size_t abase = (size_t)b1 * sA1 + (size_t)b2 * sA2;
    const size_t bbase = (size_t)b1 * sB1 + (size_t)b2 * sB2;
    const size_t cbase = (size_t)b1 * sC1 + (size_t)b2 * sC2;
    const int m0 = blockIdx.y * 128, n0 = blockIdx.x * 128;
    const int wm = (wid & 1) * 64, wn = (wid >> 1) * 32;

    // ---- per-thread load plan: 4 chunks of 16B (A, B tiles) ----
    const __half* srcp[4];
    uint32_t doff[4];
    #pragma unroll
    for (int q = 0; q < 4; q++) {
        int ci = q * 256 + tid;
        int u = ci >> 9;                 // 0:A 1:B
        int r = (ci >> 2) & 127;
        int c16 = ci & 3;
        doff[q] = (uint32_t)(u * TILE_B + r * (LDS * 2) + c16 * 16);
        if (u == 0) {
            int gr = m0 + r;
            size_t ro = abase + (size_t)gr * lda + (convA ? (size_t)(gr >> 8) * 2048 : 0) + c16 * 8;
            srcp[q] = A + ro;
        } else {
            size_t ro = bbase + (size_t)(n0 + r) * ldb + c16 * 8;
            srcp[q] = B + ro;
        }
    }

    const int nc = K / 32;
    #pragma unroll
    for (int q = 0; q < 4; q++) cp16(sbase + doff[q], srcp[q]);
    cp_commit();

    float acc[4][4][4] = {};
    const int lrowA = lane & 15, lkA = (lane >> 4) << 3;
    const int lrowB = ((lane >> 4) << 3) + (lane & 7), lkB = ((lane >> 3) & 1) << 3;

    for (int c = 0; c < nc; c++) {
        if (c + 1 < nc) {
            uint32_t st = sbase + (uint32_t)(((c + 1) & 1) * STAGE_B);
            int k0 = (c + 1) * 32;
            #pragma unroll
            for (int q = 0; q < 4; q++) cp16(st + doff[q], srcp[q] + k0);
            cp_commit();
            cp_wait<1>();
        } else {
            cp_wait<0>();
        }
        __syncthreads();

        uint32_t sa = sbase + (uint32_t)((c & 1) * STAGE_B);
        #pragma unroll
        for (int kk2 = 0; kk2 < 2; kk2++) {
            const int kk = kk2 * 16;
            uint32_t af[4][4], bf[4][2];
            #pragma unroll
            for (int mt = 0; mt < 4; mt++) {
                uint32_t ra = sa + (uint32_t)((wm + mt * 16 + lrowA) * (LDS * 2) + (kk + lkA) * 2);
                ldsm4(af[mt][0], af[mt][1], af[mt][2], af[mt][3], ra);
            }
            #pragma unroll
            for (int np = 0; np < 2; np++) {
                uint32_t rb = sa + (uint32_t)(TILE_B + (wn + np * 16 + lrowB) * (LDS * 2) + (kk + lkB) * 2);
                uint32_t h0, h1, h2, h3;
                ldsm4(h0, h1, h2, h3, rb);
                bf[np * 2][0] = h0; bf[np * 2][1] = h1;
                bf[np * 2 + 1][0] = h2; bf[np * 2 + 1][1] = h3;
            }
            // 16 accumulators each touched once -> chains naturally 16 apart
            #pragma unroll
            for (int mt = 0; mt < 4; mt++)
                #pragma unroll
                for (int nt = 0; nt < 4; nt++)
                    mma16816(acc[mt][nt], af[mt], bf[nt]);
        }
        __syncthreads();
    }

    // ---- epilogue ----
    const int qr = lane >> 2, qc = (lane & 3) * 2;
    #pragma unroll
    for (int mt = 0; mt < 4; mt++) {
        #pragma unroll
        for (int hrow = 0; hrow < 2; hrow++) {
            int grow = m0 + wm + mt * 16 + qr + hrow * 8;
            #pragma unroll
            for (int nt = 0; nt < 4; nt++) {
                int gcol = n0 + wn + nt * 8 + qc;
                float v0 = acc[mt][nt][hrow * 2 + 0] * alpha;
                float v1 = acc[mt][nt][hrow * 2 + 1] * alpha;
                if (EPI == 1 || EPI == 2 || EPI == 3) { v0 += bias[gcol]; v1 += bias[gcol + 1]; }
                if (EPI == 1) { v0 = fmaxf(v0, 0.f); v1 = fmaxf(v1, 0.f); }
                if (EPI == 3) {
                    v0 = 0.5f * v0 * (1.f + erff(v0 * 0.70710678118654752f));
                    v1 = 0.5f * v1 * (1.f + erff(v1 * 0.70710678118654752f));
                }
                size_t off = cbase + (size_t)grow * ldc + gcol;
                if (EPI == 3 || EPI == 4) {
                    __half2 ph; ph.x = __float2half(v0); ph.y = __float2half(v1);
                    *reinterpret_cast<__half2*>(Ch + off) = ph;
                } else {
                    if (EPI == 2) {
                        float2 old = *reinterpret_cast<const float2*>(C + off);
                        v0 += old.x; v1 += old.y;
                    }
                    float2 o; o.x = v0; o.y = v1;
                    *reinterpret_cast<float2*>(C + off) = o;
                }
            }
        }
    }
}

// ---------------- transpose V+T head blocks: sel=0 -> V, sel=1 -> T ----------------
__global__ void trans_vt2(const __half* __restrict__ srch,
                          __half* __restrict__ vd, __half* __restrict__ td) {
    __shared__ __half sh[32][34];
    int zz = blockIdx.z;
    int sel = zz >= BNB * H;
    int z = zz - sel * BNB * H;
    int bn = z >> 2, hh = z & 3;
    int coloff = 2 * CC + sel * CC;
    __half* dst = sel ? td : vd;
    int d0 = blockIdx.x * 32, t0 = blockIdx.y * 32;
    int tx = threadIdx.x, ty = threadIdx.y;
    #pragma unroll
    for (int i = 0; i < 4; i++) {
        int t = t0 + ty + i * 8;
        size_t src = ((size_t)(bn * T + t)) * 2048 + coloff + hh * 128 + d0 + tx;
        sh[ty + i * 8][tx] = srch[src];
    }
    __syncthreads();
    #pragma unroll
    for (int i = 0; i < 4; i++) {
        int d = d0 + ty + i * 8;
        size_t dst_i = ((size_t)z * DH + d) * T + t0 + tx;
        dst[dst_i] = sh[tx][ty + i * 8];
    }
}

// ---------------- small prep kernels ----------------
__global__ void pad_k(const float* __restrict__ x, __half* __restrict__ xp) {
    size_t total = (size_t)BNB * (T + 2) * D;
    for (size_t idx = (size_t)blockIdx.x * blockDim.x + threadIdx.x; idx < total;
         idx += (size_t)gridDim.x * blockDim.x) {
        size_t bn = idx / ((T + 2) * D);
        size_t rr = idx - bn * (T + 2) * D;
        int tt = (int)(rr >> 10);
        int i = (int)(rr & 1023);
        float v = (tt == 0 || tt == T + 1) ? 0.f : x[(bn * T + (tt - 1)) * D + i];
        xp[idx] = __float2half(v);
    }
}

__global__ void csplit_k(const float* __restrict__ W, __half* __restrict__ o) {
    int total = CC * 3 * D;
    for (int idx = blockIdx.x * blockDim.x + threadIdx.x; idx < total; idx += gridDim.x * blockDim.x) {
        int c = idx / (3 * D), j = idx % (3 * D);
        int kk = j >> 10, i = j & 1023;
        o[idx] = __float2half(W[(size_t)c * 3 * D + i * 3 + kk]);
    }
}

__global__ void wsplit_k(const float* __restrict__ W, int N, int K, __half* __restrict__ o) {
    int total = N * K;
    for (int idx = blockIdx.x * blockDim.x + threadIdx.x; idx < total; idx += gridDim.x * blockDim.x) {
        int n = idx / K, k = idx % K;
        o[idx] = __float2half(W[(size_t)k * N + n]);
    }
}

__global__ void a2_sum_k(float* __restrict__ srow) {
    int j = threadIdx.x;
    float s = 0.f;
    for (int k = 0; k < T; k++)
        s += expf(-fabsf((float)(j - k)) / 2.718281828459045f);
    srow[j] = s;
}
__global__ void a2_fill_k(const float* __restrict__ srow, __half* __restrict__ a2) {
    int i = blockIdx.x, j = threadIdx.x;
    float v = expf(-fabsf((float)(i - j)) / 2.718281828459045f) / srow[j];
    a2[i * T + j] = __float2half(v);
}
__global__ void tr1_k(const float* __restrict__ W, float* __restrict__ Wt) {
    int idx = blockIdx.x * blockDim.x + threadIdx.x;
    if (idx < CC * 32) { int c = idx / 32, o = idx % 32; Wt[idx] = W[o * CC + c]; }
}
__global__ void tr2_k(const float* __restrict__ W, float* __restrict__ Wt) {
    int idx = blockIdx.x * blockDim.x + threadIdx.x;
    if (idx < 32 * 16) { int c = idx / 16, o = idx % 16; Wt[idx] = W[o * 32 + c]; }
}

// ---------------- LayerNorm (row of 512) -> fp16 out ----------------
__global__ void ln_k(const float* __restrict__ X, __half* __restrict__ Y,
                     const float* __restrict__ g, const float* __restrict__ b) {
    int row = blockIdx.x;
    const float* x = X + (size_t)row * CC;
    int t = threadIdx.x;
    float v0 = x[t], v1 = x[t + 256];
    __shared__ float red[256];
    red[t] = v0 + v1;
    __syncthreads();
    for (int s = 128; s > 0; s >>= 1) { if (t < s) red[t] += red[t + s]; __syncthreads(); }
    float mean = red[0] * (1.f / CC);
    __syncthreads();
    float d0 = v0 - mean, d1 = v1 - mean;
    red[t] = d0 * d0 + d1 * d1;
    __syncthreads();
    for (int s = 128; s > 0; s >>= 1) { if (t < s) red[t] += red[t + s]; __syncthreads(); }
    float rstd = rsqrtf(red[0] * (1.f / CC) + EPS);
    size_t base = (size_t)row * CC;
    Y[base + t]       = __float2half(d0 * rstd * g[t] + b[t]);
    Y[base + t + 256] = __float2half(d1 * rstd * g[t + 256] + b[t + 256]);
}

// ---------------- softmax over rows of 256, fp16 out ----------------
__global__ void softmax_k(const float* __restrict__ S, __half* __restrict__ Sh) {
    size_t row = blockIdx.x;
    const float* p = S + row * T;
    int t = threadIdx.x;
    float v = p[t];
    __shared__ float red[256];
    red[t] = v;
    __syncthreads();
    for (int s = 128; s > 0; s >>= 1) { if (t < s) red[t] = fmaxf(red[t], red[t + s]); __syncthreads(); }
    float mx = red[0];
    __syncthreads();
    float e = expf(v - mx);
    red[t] = e;
    __syncthreads();
    for (int s = 128; s > 0; s >>= 1) { if (t < s) red[t] += red[t + s]; __syncthreads(); }
    Sh[row * T + t] = __float2half(e / red[0]);
}

// ---------------- fused head ----------------
__global__ void head_k(const float* __restrict__ Hh,
                       const float* __restrict__ W1t, const float* __restrict__ c1_b,
                       const float* __restrict__ bn1_g, const float* __restrict__ bn1_b,
                       const float* __restrict__ bn1_m, const float* __restrict__ bn1_v,
                       const float* __restrict__ W2t, const float* __restrict__ c2_b,
                       const float* __restrict__ bn2_g, const float* __restrict__ bn2_b,
                       const float* __restrict__ bn2_m, const float* __restrict__ bn2_v,
                       const float* __restrict__ c3_W, const float* __restrict__ c3_b,
                       float* __restrict__ score, float* __restrict__ dist) {
    int warp = threadIdx.x >> 5, lane = threadIdx.x & 31;
    size_t row = (size_t)blockIdx.x * 8 + warp;
    __shared__ float hs[8][CC];
    for (int idx = threadIdx.x; idx < 8 * CC; idx += 256) {
        int r = idx >> 9, c = idx & (CC - 1);
        hs[r][c] = Hh[((size_t)blockIdx.x * 8 + r) * CC + c];
    }
    __syncthreads();
    int o = lane;
    float x1 = c1_b[o];
    #pragma unroll 8
    for (int c = 0; c < CC; c++)
        x1 = fmaf(hs[warp][c], W1t[c * 32 + o], x1);
    float dd = x1 - bn1_m[o];
    float d1 = dd * dd / bn1_v[o];
    #pragma unroll
    for (int s = 16; s; s >>= 1) d1 += __shfl_xor_sync(0xffffffffu, d1, s);
    float y1 = fmaxf((x1 - bn1_m[o]) * rsqrtf(bn1_v[o] + EPS) * bn1_g[o] + bn1_b[o], 0.f);
    float x2 = (lane < 16) ? c2_b[lane] : 0.f;
    #pragma unroll
    for (int c = 0; c < 32; c++) {
        float yc = __shfl_sync(0xffffffffu, y1, c);
        if (lane < 16) x2 = fmaf(yc, W2t[c * 16 + lane], x2);
    }
    float d2 = 0.f;
    if (lane < 16) { float e = x2 - bn2_m[lane]; d2 = e * e / bn2_v[lane]; }
    #pragma unroll
    for (int s = 16; s; s >>= 1) d2 += __shfl_xor_sync(0xffffffffu, d2, s);
    float y2 = 0.f;
    if (lane < 16)
        y2 = fmaxf((x2 - bn2_m[lane]) * rsqrtf(bn2_v[lane] + EPS) * bn2_g[lane] + bn2_b[lane], 0.f);
    float sacc = (lane < 16) ? y2 * c3_W[lane] : 0.f;
    #pragma unroll
    for (int s = 16; s; s >>= 1) sacc += __shfl_xor_sync(0xffffffffu, sacc, s);
    if (lane == 0) {
        score[row] = 1.f / (1.f + expf(-(sacc + c3_b[0])));
        dist[row] = sqrtf(d1) + sqrtf(d2);
    }
}

__global__ void final_k(const float* __restrict__ dist, const float* __restrict__ score,
                        float* __restrict__ out) {
    int idx = blockIdx.x * blockDim.x + threadIdx.x;
    if (idx >= BATCH * T) return;
    int b = idx / T, t = idx % T;
    float sd = 0.f, ss = 0.f;
    for (int n = 0; n < NCROP; n++) {
        size_t r = ((size_t)(b * NCROP + n)) * T + t;
        sd += dist[r];
        ss += score[r];
    }
    out[idx] = (sd * 0.1f) * (ss * 0.1f);
}

// ---------------- host launch ----------------
template<typename P>
static P symaddr_t(const void* sym) {
    void* p = nullptr;
    cudaGetSymbolAddress(&p, sym);
    return (P)p;
}

extern "C" void kernel_launch(void* const* d_in, const int* in_sizes, int n_in,
                              void* d_out, int out_size) {
    const float* x     = (const float*)d_in[0];
    const float* W_emb = (const float*)d_in[1];
    const float* b_emb = (const float*)d_in[2];
    const float* ln1_g = (const float*)d_in[3];
    const float* ln1_b = (const float*)d_in[4];
    const float* W_qkv = (const float*)d_in[5];
    const float* W_o   = (const float*)d_in[6];
    const float* b_o   = (const float*)d_in[7];
    const float* ln2_g = (const float*)d_in[8];
    const float* ln2_b = (const float*)d_in[9];
    const float* W_f1  = (const float*)d_in[10];
    const float* b_f1  = (const float*)d_in[11];
    const float* W_f2  = (const float*)d_in[12];
    const float* b_f2  = (const float*)d_in[13];
    const float* c1_W  = (const float*)d_in[14];
    const float* c1_b  = (const float*)d_in[15];
    const float* bn1_g = (const float*)d_in[16];
    const float* bn1_b = (const float*)d_in[17];
    const float* bn1_m = (const float*)d_in[18];
    const float* bn1_v = (const float*)d_in[19];
    const float* c2_W  = (const float*)d_in[20];
    const float* c2_b  = (const float*)d_in[21];
    const float* bn2_g = (const float*)d_in[22];
    const float* bn2_b = (const float*)d_in[23];
    const float* bn2_m = (const float*)d_in[24];
    const float* bn2_v = (const float*)d_in[25];
    const float* c3_W  = (const float*)d_in[26];
    const float* c3_b  = (const float*)d_in[27];
    float* out = (float*)d_out;

    __half* xp = symaddr_t<__half*>(g_xp);
    __half* bte = symaddr_t<__half*>(g_bte);
    __half* z = symaddr_t<__half*>(g_z);
    __half* f1 = symaddr_t<__half*>(g_f1);
    __half* O = symaddr_t<__half*>(g_O);
    __half* qkvt = symaddr_t<__half*>(g_qkvt);
    __half* Shp = symaddr_t<__half*>(g_Sh);
    __half* vt = symaddr_t<__half*>(g_vt);
    __half* tt = symaddr_t<__half*>(g_tt);
    __half* a2 = symaddr_t<__half*>(g_a2);
    __half* wqkv = symaddr_t<__half*>(g_wqkv);
    __half* wo = symaddr_t<__half*>(g_wo);
    __half* wf1 = symaddr_t<__half*>(g_wf1);
    __half* wf2 = symaddr_t<__half*>(g_wf2);
    float* h    = symaddr_t<float*>(g_h);
    float* S    = symaddr_t<float*>(g_S);
    float* arow = symaddr_t<float*>(g_arow);
    float* w1t  = symaddr_t<float*>(g_w1t);
    float* w2t  = symaddr_t<float*>(g_w2t);
    float* score = symaddr_t<float*>(g_score);
    float* dist  = symaddr_t<float*>(g_dist);

    const float scale = 0.08838834764831845f;  // 1/sqrt(128)
    cudaFuncSetAttribute(mma_gemm<0>, cudaFuncAttributeMaxDynamicSharedMemorySize, MM_SMEM);
    cudaFuncSetAttribute(mma_gemm<1>, cudaFuncAttributeMaxDynamicSharedMemorySize, MM_SMEM);
    cudaFuncSetAttribute(mma_gemm<2>, cudaFuncAttributeMaxDynamicSharedMemorySize, MM_SMEM);
    cudaFuncSetAttribute(mma_gemm<3>, cudaFuncAttributeMaxDynamicSharedMemorySize, MM_SMEM);
    cudaFuncSetAttribute(mma_gemm<4>, cudaFuncAttributeMaxDynamicSharedMemorySize, MM_SMEM);

    // prep ordered so conv GEMM is my 4th launch (ncu capture target)
    {
        size_t total = (size_t)BNB * (T + 2) * D;
        pad_k<<<(int)((total + 255) / 256), 256>>>(x, xp);                             // 1
        csplit_k<<<(3 * D * CC + 255) / 256, 256>>>(W_emb, bte);                       // 2
        wsplit_k<<<(4 * CC * CC + 255) / 256, 256>>>(W_qkv, 4 * CC, CC, wqkv);         // 3
        // conv-as-GEMM: M=40960, N=512, K=3072 (overlapping-window A)                 // 4 <- profiled
        mma_gemm<1><<<dim3(CC / 128, MALL / 128), 256, MM_SMEM>>>(
            xp, 1024, 1, bte, 3 * D, 3 * D, 1.f,
            h, nullptr, CC, b_emb, 1, 0, 0, 0, 0, 0, 0);
        wsplit_k<<<(2 * CC * CC + 255) / 256, 256>>>(W_o, CC, 2 * CC, wo);
        wsplit_k<<<(CC * CC + 255) / 256, 256>>>(W_f1, CC, CC, wf1);
        wsplit_k<<<(CC * CC + 255) / 256, 256>>>(W_f2, CC, CC, wf2);
        for (int l = 1; l < LDEP; l++) {
            wsplit_k<<<(4 * CC * CC + 255) / 256, 256>>>(W_qkv + (size_t)l * CC * 4 * CC, 4 * CC, CC,
                                                         wqkv + (size_t)l * 4 * CC * CC);
            wsplit_k<<<(2 * CC * CC + 255) / 256, 256>>>(W_o + (size_t)l * 2 * CC * CC, CC, 2 * CC,
                                                         wo + (size_t)l * CC * 2 * CC);
            wsplit_k<<<(CC * CC + 255) / 256, 256>>>(W_f1 + (size_t)l * CC * CC, CC, CC,
                                                     wf1 + (size_t)l * CC * CC);
            wsplit_k<<<(CC * CC + 255) / 256, 256>>>(W_f2 + (size_t)l * CC * CC, CC, CC,
                                                     wf2 + (size_t)l * CC * CC);
        }
    }

    // fixed positional attention map (fp16)
    a2_sum_k<<<1, 256>>>(arow);
    a2_fill_k<<<T, 256>>>(arow, a2);

    const long long rowstr = (long long)T * 4 * CC;   // qkvt batch row stride per bn
    for (int l = 0; l < LDEP; l++) {
        ln_k<<<MALL, 256>>>(h, z, ln1_g + l * CC, ln1_b + l * CC);
        // qkvt = z @ W_qkv[l] -> fp16 (M=40960, N=2048, K=512)
        mma_gemm<4><<<dim3(4 * CC / 128, MALL / 128), 256, MM_SMEM>>>(
            z, CC, 0, wqkv + (size_t)l * 4 * CC * CC,
            CC, CC, 1.f, nullptr, qkvt, 4 * CC, nullptr, 1, 0, 0, 0, 0, 0, 0);
        // S = scale * Q @ K^T  (batched bn x H, M=N=256, K=128); K block at col offset CC
        mma_gemm<0><<<dim3(2, 2, BNB * H), 256, MM_SMEM>>>(
            qkvt, 4 * CC, 0, qkvt + CC, 4 * CC, DH, scale,
            S, nullptr, T, nullptr,
            H, rowstr, DH, rowstr, DH, (long long)H * T * T, (long long)T * T);
        softmax_k<<<BNB * H * T, 256>>>(S, Shp);
        // transpose V and T head blocks to [bn,h,d,t]
        trans_vt2<<<dim3(DH / 32, T / 32, 2 * BNB * H), dim3(32, 8)>>>(qkvt, vt, tt);
        // o1 = S @ V  (batched bn x H, M=256, N=128, K=256)
        mma_gemm<4><<<dim3(1, 2, BNB * H), 256, MM_SMEM>>>(
            Shp, T, 0, vt, T, T, 1.f,
            nullptr, O, 2 * CC, nullptr,
            H, (long long)H * T * T, (long long)T * T,
            (long long)H * DH * T, (long long)DH * T,
            (long long)T * 2 * CC, 2 * DH);
        // o2 = a2 @ Tm
        mma_gemm<4><<<dim3(1, 2, BNB * H), 256, MM_SMEM>>>(
            a2, T, 0, tt, T, T, 1.f,
            nullptr, O + DH, 2 * CC, nullptr,
            H, 0, 0,
            (long long)H * DH * T, (long long)DH * T,
            (long long)T * 2 * CC, 2 * DH);
        // h = O @ W_o[l] + b_o + h   (M=40960, N=512, K=1024)
        mma_gemm<2><<<dim3(CC / 128, MALL / 128), 256, MM_SMEM>>>(
            O, 2 * CC, 0, wo + (size_t)l * CC * 2 * CC,
            2 * CC, 2 * CC, 1.f, h, nullptr, CC, b_o + l * CC, 1, 0, 0, 0, 0, 0, 0);
        // FF
        ln_k<<<MALL, 256>>>(h, z, ln2_g + l * CC, ln2_b + l * CC);
        mma_gemm<3><<<dim3(CC / 128, MALL / 128), 256, MM_SMEM>>>(
            z, CC, 0, wf1 + (size_t)l * CC * CC,
            CC, CC, 1.f, nullptr, f1, CC, b_f1 + l * CC, 1, 0, 0, 0, 0, 0, 0);
        mma_gemm<2><<<dim3(CC / 128, MALL / 128), 256, MM_SMEM>>>(
            f1, CC, 0, wf2 + (size_t)l * CC * CC,
            CC, CC, 1.f, h, nullptr, CC, b_f2 + l * CC, 1, 0, 0, 0, 0, 0, 0);
    }

    // head
    tr1_k<<<(CC * 32 + 255) / 256, 256>>>(c1_W, w1t);
    tr2_k<<<2, 256>>>(c2_W, w2t);
    head_k<<<MALL / 8, 256>>>(h, w1t, c1_b, bn1_g, bn1_b, bn1_m, bn1_v,
                              w2t, c2_b, bn2_g, bn2_b, bn2_m, bn2_v,
                              c3_W, c3_b, score, dist);
    final_k<<<(BATCH * T + 255) / 256, 256>>>(dist, score, out);
}

// round 15
// speedup vs baseline: 2.9793x; 1.3286x over previous
#include <cuda_runtime.h>
#include <cuda_fp16.h>
#include <math.h>
#include <stdint.h>

// Problem constants
constexpr int BATCH = 16, NCROP = 10, BNB = 160, T = 256, D = 1024, CC = 512;
constexpr int H = 4, DH = 128, LDEP = 2;
constexpr int MALL = BNB * T;               // 40960 rows
constexpr float EPS = 1e-5f;

// ---------------- device scratch (static, no allocation) ----------------
__device__ __align__(16) __half g_xp[(size_t)BNB * (T + 2) * D];
__device__ __align__(16) __half g_bte[CC * 3 * D];
__device__ __align__(16) __half g_z[(size_t)MALL * CC];
__device__ __align__(16) __half g_f1[(size_t)MALL * CC];
__device__ __align__(16) __half g_O[(size_t)MALL * 2 * CC];
__device__ __align__(16) __half g_qkvt[(size_t)MALL * 4 * CC];
__device__ __align__(16) __half g_Sh[(size_t)BNB * H * T * T];
__device__ __align__(16) __half g_vt[(size_t)BNB * H * DH * T];
__device__ __align__(16) __half g_tt[(size_t)BNB * H * DH * T];
__device__ __align__(16) __half g_a2[T * T];
__device__ __align__(16) __half g_wqkv[LDEP * 4 * CC * CC];
__device__ __align__(16) __half g_wo[LDEP * CC * 2 * CC];
__device__ __align__(16) __half g_wf1[LDEP * CC * CC];
__device__ __align__(16) __half g_wf2[LDEP * CC * CC];
// fp32 buffers
__device__ __align__(16) float g_h[(size_t)MALL * CC];
__device__ __align__(16) float g_S[(size_t)BNB * H * T * T];
__device__ float g_arow[T];
__device__ float g_w1t[CC * 32];
__device__ float g_w2t[32 * 16];
__device__ float g_score[MALL];
__device__ float g_dist[MALL];

// ---------------- helpers ----------------
__device__ __forceinline__ uint32_t smem_u32(const void* p) {
    uint32_t a;
    asm("{ .reg .u64 t; cvta.to.shared.u64 t, %1; cvt.u32.u64 %0, t; }" : "=r"(a) : "l"(p));
    return a;
}
__device__ __forceinline__ void cp16(uint32_t dst, const void* src) {
    asm volatile("cp.async.cg.shared.global [%0], [%1], 16;" :: "r"(dst), "l"(src));
}
__device__ __forceinline__ void cp_commit() {
    asm volatile("cp.async.commit_group;" ::: "memory");
}
template<int N>
__device__ __forceinline__ void cp_wait() {
    asm volatile("cp.async.wait_group %0;" :: "n"(N) : "memory");
}
__device__ __forceinline__ void ldsm4(uint32_t& r0, uint32_t& r1, uint32_t& r2, uint32_t& r3, uint32_t addr) {
    asm volatile("ldmatrix.sync.aligned.m8n8.x4.shared.b16 {%0,%1,%2,%3}, [%4];"
                 : "=r"(r0), "=r"(r1), "=r"(r2), "=r"(r3) : "r"(addr));
}
__device__ __forceinline__ void mma16816(float* c, const uint32_t* a, const uint32_t* b) {
    asm volatile(
        "mma.sync.aligned.m16n8k16.row.col.f32.f16.f16.f32 "
        "{%0,%1,%2,%3}, {%4,%5,%6,%7}, {%8,%9}, {%0,%1,%2,%3};"
        : "+f"(c[0]), "+f"(c[1]), "+f"(c[2]), "+f"(c[3])
        : "r"(a[0]), "r"(a[1]), "r"(a[2]), "r"(a[3]), "r"(b[0]), "r"(b[1]));
}

// ================= plain fp16 HMMA GEMM: C(M,N) = alpha * A(M,K) @ B(N,K)^T =================
// 128x128 CTA tile, 8 warps of 64x32, BK=32, cp.async double buffer, two-level batch, 2 CTA/SM.
// EPI: 0 fp32 store (alpha); 1 +bias relu fp32; 2 +bias +C fp32; 3 +bias gelu fp16; 4 plain fp16.
constexpr int LDS = 40;
constexpr int TILE_B = 128 * LDS * 2;        // 10240 bytes per tile
constexpr int STAGE_B = 2 * TILE_B;          // A, B
constexpr int MM_SMEM = 2 * STAGE_B;         // 40960

template<int EPI>
__global__ void __launch_bounds__(256, 2) mma_gemm(
    const __half* __restrict__ A, int lda, int convA,
    const __half* __restrict__ B, int ldb, int K, float alpha,
    float* __restrict__ C, __half* __restrict__ Ch,
    int ldc, const float* __restrict__ bias,
    int H2, long long sA1, long long sA2, long long sB1, long long sB2,
    long long sC1, long long sC2)
{
    extern __shared__ __align__(1024) char smem[];
    const uint32_t sbase = smem_u32(smem);
    const int tid = threadIdx.x, lane = tid & 31, wid = tid >> 5;
    const int bz = blockIdx.z;
    const int b1 = bz / H2, b2 = bz - b1 * H2;
    const size_t abase = (size_t)b1 * sA1 + (size_t)b2 * sA2;
    const size_t bbase = (size_t)b1 * sB1 + (size_t)b2 * sB2;
    const size_t cbase = (size_t)b1 * sC1 + (size_t)b2 * sC2;
    const int m0 = blockIdx.y * 128, n0 = blockIdx.x * 128;
    const int wm = (wid & 1) * 64, wn = (wid >> 1) * 32;

    const __half* srcp[4];
    uint32_t doff[4];
    #pragma unroll
    for (int q = 0; q < 4; q++) {
        int ci = q * 256 + tid;
        int u = ci >> 9;
        int r = (ci >> 2) & 127;
        int c16 = ci & 3;
        doff[q] = (uint32_t)(u * TILE_B + r * (LDS * 2) + c16 * 16);
        if (u == 0) {
            int gr = m0 + r;
            size_t ro = abase + (size_t)gr * lda + (convA ? (size_t)(gr >> 8) * 2048 : 0) + c16 * 8;
            srcp[q] = A + ro;
        } else {
            size_t ro = bbase + (size_t)(n0 + r) * ldb + c16 * 8;
            srcp[q] = B + ro;
        }
    }

    const int nc = K / 32;
    #pragma unroll
    for (int q = 0; q < 4; q++) cp16(sbase + doff[q], srcp[q]);
    cp_commit();

    float acc[4][4][4] = {};
    const int lrowA = lane & 15, lkA = (lane >> 4) << 3;
    const int lrowB = ((lane >> 4) << 3) + (lane & 7), lkB = ((lane >> 3) & 1) << 3;

    for (int c = 0; c < nc; c++) {
        if (c + 1 < nc) {
            uint32_t st = sbase + (uint32_t)(((c + 1) & 1) * STAGE_B);
            int k0 = (c + 1) * 32;
            #pragma unroll
            for (int q = 0; q < 4; q++) cp16(st + doff[q], srcp[q] + k0);
            cp_commit();
            cp_wait<1>();
        } else {
            cp_wait<0>();
        }
        __syncthreads();

        uint32_t sa = sbase + (uint32_t)((c & 1) * STAGE_B);
        #pragma unroll
        for (int kk2 = 0; kk2 < 2; kk2++) {
            const int kk = kk2 * 16;
            uint32_t af[4][4], bf[4][2];
            #pragma unroll
            for (int mt = 0; mt < 4; mt++) {
                uint32_t ra = sa + (uint32_t)((wm + mt * 16 + lrowA) * (LDS * 2) + (kk + lkA) * 2);
                ldsm4(af[mt][0], af[mt][1], af[mt][2], af[mt][3], ra);
            }
            #pragma unroll
            for (int np = 0; np < 2; np++) {
                uint32_t rb = sa + (uint32_t)(TILE_B + (wn + np * 16 + lrowB) * (LDS * 2) + (kk + lkB) * 2);
                uint32_t h0, h1, h2, h3;
                ldsm4(h0, h1, h2, h3, rb);
                bf[np * 2][0] = h0; bf[np * 2][1] = h1;
                bf[np * 2 + 1][0] = h2; bf[np * 2 + 1][1] = h3;
            }
            #pragma unroll
            for (int mt = 0; mt < 4; mt++)
                #pragma unroll
                for (int nt = 0; nt < 4; nt++)
                    mma16816(acc[mt][nt], af[mt], bf[nt]);
        }
        __syncthreads();
    }

    const int qr = lane >> 2, qc = (lane & 3) * 2;
    #pragma unroll
    for (int mt = 0; mt < 4; mt++) {
        #pragma unroll
        for (int hrow = 0; hrow < 2; hrow++) {
            int grow = m0 + wm + mt * 16 + qr + hrow * 8;
            #pragma unroll
            for (int nt = 0; nt < 4; nt++) {
                int gcol = n0 + wn + nt * 8 + qc;
                float v0 = acc[mt][nt][hrow * 2 + 0] * alpha;
                float v1 = acc[mt][nt][hrow * 2 + 1] * alpha;
                if (EPI == 1 || EPI == 2 || EPI == 3) { v0 += bias[gcol]; v1 += bias[gcol + 1]; }
                if (EPI == 1) { v0 = fmaxf(v0, 0.f); v1 = fmaxf(v1, 0.f); }
                if (EPI == 3) {
                    v0 = 0.5f * v0 * (1.f + erff(v0 * 0.70710678118654752f));
                    v1 = 0.5f * v1 * (1.f + erff(v1 * 0.70710678118654752f));
                }
                size_t off = cbase + (size_t)grow * ldc + gcol;
                if (EPI == 3 || EPI == 4) {
                    __half2 ph; ph.x = __float2half(v0); ph.y = __float2half(v1);
                    *reinterpret_cast<__half2*>(Ch + off) = ph;
                } else {
                    if (EPI == 2) {
                        float2 old = *reinterpret_cast<const float2*>(C + off);
                        v0 += old.x; v1 += old.y;
                    }
                    float2 o; o.x = v0; o.y = v1;
                    *reinterpret_cast<float2*>(C + off) = o;
                }
            }
        }
    }
}

// ---------------- transpose V+T head blocks, half2-vectorized ----------------
__global__ void trans_vt2(const __half* __restrict__ srch,
                          __half* __restrict__ vd, __half* __restrict__ td) {
    __shared__ __half sh[32][34];
    int zz = blockIdx.z;
    int sel = zz >= BNB * H;
    int z = zz - sel * BNB * H;
    int bn = z >> 2, hh = z & 3;
    int coloff = 2 * CC + sel * CC;
    __half* dst = sel ? td : vd;
    int d0 = blockIdx.x * 32, t0 = blockIdx.y * 32;
    int tx = threadIdx.x;   // 0..15: half2 column
    int ty = threadIdx.y;   // 0..15
    #pragma unroll
    for (int j = 0; j < 2; j++) {
        int tl = ty + j * 16;
        __half2 v = *reinterpret_cast<const __half2*>(
            srch + ((size_t)(bn * T + t0 + tl)) * 2048 + coloff + hh * 128 + d0 + 2 * tx);
        sh[tl][2 * tx] = v.x;
        sh[tl][2 * tx + 1] = v.y;
    }
    __syncthreads();
    #pragma unroll
    for (int j = 0; j < 2; j++) {
        int dl = ty + j * 16;
        __half2 o;
        o.x = sh[2 * tx][dl];
        o.y = sh[2 * tx + 1][dl];
        *reinterpret_cast<__half2*>(dst + ((size_t)z * DH + d0 + dl) * T + t0 + 2 * tx) = o;
    }
}

// ---------------- vectorized pad (float4 -> 4 halves) ----------------
__global__ void pad_k(const float* __restrict__ x, __half* __restrict__ xp) {
    size_t total4 = (size_t)BNB * (T + 2) * D / 4;
    const int ROW4 = D / 4;                  // 256 float4 per row
    for (size_t idx = (size_t)blockIdx.x * blockDim.x + threadIdx.x; idx < total4;
         idx += (size_t)gridDim.x * blockDim.x) {
        size_t bn = idx / ((T + 2) * ROW4);
        size_t rr = idx - bn * (T + 2) * ROW4;
        int tt = (int)(rr / ROW4);
        int i4 = (int)(rr - (size_t)tt * ROW4);
        __half2 h0, h1;
        if (tt == 0 || tt == T + 1) {
            h0.x = __float2half(0.f); h0.y = h0.x; h1 = h0;
        } else {
            float4 v = *reinterpret_cast<const float4*>(x + ((bn * T + (tt - 1)) * (size_t)D + i4 * 4));
            h0 = __floats2half2_rn(v.x, v.y);
            h1 = __floats2half2_rn(v.z, v.w);
        }
        __half2* dst = reinterpret_cast<__half2*>(xp) + idx * 2;
        dst[0] = h0; dst[1] = h1;
    }
}

__global__ void csplit_k(const float* __restrict__ W, __half* __restrict__ o) {
    int total = CC * 3 * D;
    for (int idx = blockIdx.x * blockDim.x + threadIdx.x; idx < total; idx += gridDim.x * blockDim.x) {
        int c = idx / (3 * D), j = idx % (3 * D);
        int kk = j >> 10, i = j & 1023;
        o[idx] = __float2half(W[(size_t)c * 3 * D + i * 3 + kk]);
    }
}

__global__ void wsplit_k(const float* __restrict__ W, int N, int K, __half* __restrict__ o) {
    int total = N * K;
    for (int idx = blockIdx.x * blockDim.x + threadIdx.x; idx < total; idx += gridDim.x * blockDim.x) {
        int n = idx / K, k = idx % K;
        o[idx] = __float2half(W[(size_t)k * N + n]);
    }
}

__global__ void a2_sum_k(float* __restrict__ srow) {
    int j = threadIdx.x;
    float s = 0.f;
    for (int k = 0; k < T; k++)
        s += expf(-fabsf((float)(j - k)) / 2.718281828459045f);
    srow[j] = s;
}
__global__ void a2_fill_k(const float* __restrict__ srow, __half* __restrict__ a2) {
    int i = blockIdx.x, j = threadIdx.x;
    float v = expf(-fabsf((float)(i - j)) / 2.718281828459045f) / srow[j];
    a2[i * T + j] = __float2half(v);
}
__global__ void tr1_k(const float* __restrict__ W, float* __restrict__ Wt) {
    int idx = blockIdx.x * blockDim.x + threadIdx.x;
    if (idx < CC * 32) { int c = idx / 32, o = idx % 32; Wt[idx] = W[o * CC + c]; }
}
__global__ void tr2_k(const float* __restrict__ W, float* __restrict__ Wt) {
    int idx = blockIdx.x * blockDim.x + threadIdx.x;
    if (idx < 32 * 16) { int c = idx / 16, o = idx % 16; Wt[idx] = W[o * 32 + c]; }
}

// ---------------- LayerNorm: warp per row, shuffle-only, float4 I/O ----------------
__global__ void ln_k(const float* __restrict__ X, __half* __restrict__ Y,
                     const float* __restrict__ g, const float* __restrict__ b) {
    int warp = threadIdx.x >> 5, lane = threadIdx.x & 31;
    size_t row = (size_t)blockIdx.x * 8 + warp;
    const float4* x4 = reinterpret_cast<const float4*>(X + row * CC);
    float4 v[4];
    float s = 0.f;
    #pragma unroll
    for (int k = 0; k < 4; k++) {
        v[k] = x4[k * 32 + lane];
        s += v[k].x + v[k].y + v[k].z + v[k].w;
    }
    #pragma unroll
    for (int o = 16; o; o >>= 1) s += __shfl_xor_sync(0xffffffffu, s, o);
    float mean = s * (1.f / CC);
    float q = 0.f;
    #pragma unroll
    for (int k = 0; k < 4; k++) {
        float a0 = v[k].x - mean, a1 = v[k].y - mean, a2 = v[k].z - mean, a3 = v[k].w - mean;
        q += a0 * a0 + a1 * a1 + a2 * a2 + a3 * a3;
    }
    #pragma unroll
    for (int o = 16; o; o >>= 1) q += __shfl_xor_sync(0xffffffffu, q, o);
    float rstd = rsqrtf(q * (1.f / CC) + EPS);
    __half2* y2 = reinterpret_cast<__half2*>(Y + row * CC);
    const float4* g4 = reinterpret_cast<const float4*>(g);
    const float4* b4 = reinterpret_cast<const float4*>(b);
    #pragma unroll
    for (int k = 0; k < 4; k++) {
        int idx = k * 32 + lane;
        float4 gg = g4[idx], bb = b4[idx];
        float y0 = (v[k].x - mean) * rstd * gg.x + bb.x;
        float y1 = (v[k].y - mean) * rstd * gg.y + bb.y;
        float y2v = (v[k].z - mean) * rstd * gg.z + bb.z;
        float y3 = (v[k].w - mean) * rstd * gg.w + bb.w;
        y2[idx * 2]     = __floats2half2_rn(y0, y1);
        y2[idx * 2 + 1] = __floats2half2_rn(y2v, y3);
    }
}

// ---------------- softmax: warp per row of 256, shuffle-only ----------------
__global__ void softmax_k(const float* __restrict__ S, __half* __restrict__ Sh) {
    int warp = threadIdx.x >> 5, lane = threadIdx.x & 31;
    size_t row = (size_t)blockIdx.x * 8 + warp;
    const float4* p4 = reinterpret_cast<const float4*>(S + row * T);
    float4 a = p4[lane], b = p4[32 + lane];
    float mx = fmaxf(fmaxf(fmaxf(a.x, a.y), fmaxf(a.z, a.w)),
                     fmaxf(fmaxf(b.x, b.y), fmaxf(b.z, b.w)));
    #pragma unroll
    for (int o = 16; o; o >>= 1) mx = fmaxf(mx, __shfl_xor_sync(0xffffffffu, mx, o));
    float e[8];
    e[0] = expf(a.x - mx); e[1] = expf(a.y - mx); e[2] = expf(a.z - mx); e[3] = expf(a.w - mx);
    e[4] = expf(b.x - mx); e[5] = expf(b.y - mx); e[6] = expf(b.z - mx); e[7] = expf(b.w - mx);
    float s = e[0] + e[1] + e[2] + e[3] + e[4] + e[5] + e[6] + e[7];
    #pragma unroll
    for (int o = 16; o; o >>= 1) s += __shfl_xor_sync(0xffffffffu, s, o);
    float inv = 1.f / s;
    __half2* o2 = reinterpret_cast<__half2*>(Sh + row * T);
    o2[lane * 2]           = __floats2half2_rn(e[0] * inv, e[1] * inv);
    o2[lane * 2 + 1]       = __floats2half2_rn(e[2] * inv, e[3] * inv);
    o2[(32 + lane) * 2]     = __floats2half2_rn(e[4] * inv, e[5] * inv);
    o2[(32 + lane) * 2 + 1] = __floats2half2_rn(e[6] * inv, e[7] * inv);
}

// ---------------- fused head ----------------
__global__ void head_k(const float* __restrict__ Hh,
                       const float* __restrict__ W1t, const float* __restrict__ c1_b,
                       const float* __restrict__ bn1_g, const float* __restrict__ bn1_b,
                       const float* __restrict__ bn1_m, const float* __restrict__ bn1_v,
                       const float* __restrict__ W2t, const float* __restrict__ c2_b,
                       const float* __restrict__ bn2_g, const float* __restrict__ bn2_b,
                       const float* __restrict__ bn2_m, const float* __restrict__ bn2_v,
                       const float* __restrict__ c3_W, const float* __restrict__ c3_b,
                       float* __restrict__ score, float* __restrict__ dist) {
    int warp = threadIdx.x >> 5, lane = threadIdx.x & 31;
    size_t row = (size_t)blockIdx.x * 8 + warp;
    __shared__ float hs[8][CC];
    for (int idx = threadIdx.x; idx < 8 * CC; idx += 256) {
        int r = idx >> 9, c = idx & (CC - 1);
        hs[r][c] = Hh[((size_t)blockIdx.x * 8 + r) * CC + c];
    }
    __syncthreads();
    int o = lane;
    float x1 = c1_b[o];
    #pragma unroll 8
    for (int c = 0; c < CC; c++)
        x1 = fmaf(hs[warp][c], W1t[c * 32 + o], x1);
    float dd = x1 - bn1_m[o];
    float d1 = dd * dd / bn1_v[o];
    #pragma unroll
    for (int s = 16; s; s >>= 1) d1 += __shfl_xor_sync(0xffffffffu, d1, s);
    float y1 = fmaxf((x1 - bn1_m[o]) * rsqrtf(bn1_v[o] + EPS) * bn1_g[o] + bn1_b[o], 0.f);
    float x2 = (lane < 16) ? c2_b[lane] : 0.f;
    #pragma unroll
    for (int c = 0; c < 32; c++) {
        float yc = __shfl_sync(0xffffffffu, y1, c);
        if (lane < 16) x2 = fmaf(yc, W2t[c * 16 + lane], x2);
    }
    float d2 = 0.f;
    if (lane < 16) { float e = x2 - bn2_m[lane]; d2 = e * e / bn2_v[lane]; }
    #pragma unroll
    for (int s = 16; s; s >>= 1) d2 += __shfl_xor_sync(0xffffffffu, d2, s);
    float y2 = 0.f;
    if (lane < 16)
        y2 = fmaxf((x2 - bn2_m[lane]) * rsqrtf(bn2_v[lane] + EPS) * bn2_g[lane] + bn2_b[lane], 0.f);
    float sacc = (lane < 16) ? y2 * c3_W[lane] : 0.f;
    #pragma unroll
    for (int s = 16; s; s >>= 1) sacc += __shfl_xor_sync(0xffffffffu, sacc, s);
    if (lane == 0) {
        score[row] = 1.f / (1.f + expf(-(sacc + c3_b[0])));
        dist[row] = sqrtf(d1) + sqrtf(d2);
    }
}

__global__ void final_k(const float* __restrict__ dist, const float* __restrict__ score,
                        float* __restrict__ out) {
    int idx = blockIdx.x * blockDim.x + threadIdx.x;
    if (idx >= BATCH * T) return;
    int b = idx / T, t = idx % T;
    float sd = 0.f, ss = 0.f;
    for (int n = 0; n < NCROP; n++) {
        size_t r = ((size_t)(b * NCROP + n)) * T + t;
        sd += dist[r];
        ss += score[r];
    }
    out[idx] = (sd * 0.1f) * (ss * 0.1f);
}

// ---------------- host launch ----------------
template<typename P>
static P symaddr_t(const void* sym) {
    void* p = nullptr;
    cudaGetSymbolAddress(&p, sym);
    return (P)p;
}

extern "C" void kernel_launch(void* const* d_in, const int* in_sizes, int n_in,
                              void* d_out, int out_size) {
    const float* x     = (const float*)d_in[0];
    const float* W_emb = (const float*)d_in[1];
    const float* b_emb = (const float*)d_in[2];
    const float* ln1_g = (const float*)d_in[3];
    const float* ln1_b = (const float*)d_in[4];
    const float* W_qkv = (const float*)d_in[5];
    const float* W_o   = (const float*)d_in[6];
    const float* b_o   = (const float*)d_in[7];
    const float* ln2_g = (const float*)d_in[8];
    const float* ln2_b = (const float*)d_in[9];
    const float* W_f1  = (const float*)d_in[10];
    const float* b_f1  = (const float*)d_in[11];
    const float* W_f2  = (const float*)d_in[12];
    const float* b_f2  = (const float*)d_in[13];
    const float* c1_W  = (const float*)d_in[14];
    const float* c1_b  = (const float*)d_in[15];
    const float* bn1_g = (const float*)d_in[16];
    const float* bn1_b = (const float*)d_in[17];
    const float* bn1_m = (const float*)d_in[18];
    const float* bn1_v = (const float*)d_in[19];
    const float* c2_W  = (const float*)d_in[20];
    const float* c2_b  = (const float*)d_in[21];
    const float* bn2_g = (const float*)d_in[22];
    const float* bn2_b = (const float*)d_in[23];
    const float* bn2_m = (const float*)d_in[24];
    const float* bn2_v = (const float*)d_in[25];
    const float* c3_W  = (const float*)d_in[26];
    const float* c3_b  = (const float*)d_in[27];
    float* out = (float*)d_out;

    __half* xp = symaddr_t<__half*>(g_xp);
    __half* bte = symaddr_t<__half*>(g_bte);
    __half* z = symaddr_t<__half*>(g_z);
    __half* f1 = symaddr_t<__half*>(g_f1);
    __half* O = symaddr_t<__half*>(g_O);
    __half* qkvt = symaddr_t<__half*>(g_qkvt);
    __half* Shp = symaddr_t<__half*>(g_Sh);
    __half* vt = symaddr_t<__half*>(g_vt);
    __half* tt = symaddr_t<__half*>(g_tt);
    __half* a2 = symaddr_t<__half*>(g_a2);
    __half* wqkv = symaddr_t<__half*>(g_wqkv);
    __half* wo = symaddr_t<__half*>(g_wo);
    __half* wf1 = symaddr_t<__half*>(g_wf1);
    __half* wf2 = symaddr_t<__half*>(g_wf2);
    float* h    = symaddr_t<float*>(g_h);
    float* S    = symaddr_t<float*>(g_S);
    float* arow = symaddr_t<float*>(g_arow);
    float* w1t  = symaddr_t<float*>(g_w1t);
    float* w2t  = symaddr_t<float*>(g_w2t);
    float* score = symaddr_t<float*>(g_score);
    float* dist  = symaddr_t<float*>(g_dist);

    const float scale = 0.08838834764831845f;  // 1/sqrt(128)
    cudaFuncSetAttribute(mma_gemm<0>, cudaFuncAttributeMaxDynamicSharedMemorySize, MM_SMEM);
    cudaFuncSetAttribute(mma_gemm<1>, cudaFuncAttributeMaxDynamicSharedMemorySize, MM_SMEM);
    cudaFuncSetAttribute(mma_gemm<2>, cudaFuncAttributeMaxDynamicSharedMemorySize, MM_SMEM);
    cudaFuncSetAttribute(mma_gemm<3>, cudaFuncAttributeMaxDynamicSharedMemorySize, MM_SMEM);
    cudaFuncSetAttribute(mma_gemm<4>, cudaFuncAttributeMaxDynamicSharedMemorySize, MM_SMEM);

    // prep ordered so conv GEMM is my 4th launch (ncu capture target)
    {
        size_t total4 = (size_t)BNB * (T + 2) * D / 4;
        pad_k<<<(int)((total4 + 255) / 256), 256>>>(x, xp);                            // 1
        csplit_k<<<(3 * D * CC + 255) / 256, 256>>>(W_emb, bte);                       // 2
        wsplit_k<<<(4 * CC * CC + 255) / 256, 256>>>(W_qkv, 4 * CC, CC, wqkv);         // 3
        // conv-as-GEMM: M=40960, N=512, K=3072 (overlapping-window A)                 // 4 <- profiled
        mma_gemm<1><<<dim3(CC / 128, MALL / 128), 256, MM_SMEM>>>(
            xp, 1024, 1, bte, 3 * D, 3 * D, 1.f,
            h, nullptr, CC, b_emb, 1, 0, 0, 0, 0, 0, 0);
        wsplit_k<<<(2 * CC * CC + 255) / 256, 256>>>(W_o, CC, 2 * CC, wo);
        wsplit_k<<<(CC * CC + 255) / 256, 256>>>(W_f1, CC, CC, wf1);
        wsplit_k<<<(CC * CC + 255) / 256, 256>>>(W_f2, CC, CC, wf2);
        for (int l = 1; l < LDEP; l++) {
            wsplit_k<<<(4 * CC * CC + 255) / 256, 256>>>(W_qkv + (size_t)l * CC * 4 * CC, 4 * CC, CC,
                                                         wqkv + (size_t)l * 4 * CC * CC);
            wsplit_k<<<(2 * CC * CC + 255) / 256, 256>>>(W_o + (size_t)l * 2 * CC * CC, CC, 2 * CC,
                                                         wo + (size_t)l * CC * 2 * CC);
            wsplit_k<<<(CC * CC + 255) / 256, 256>>>(W_f1 + (size_t)l * CC * CC, CC, CC,
                                                     wf1 + (size_t)l * CC * CC);
            wsplit_k<<<(CC * CC + 255) / 256, 256>>>(W_f2 + (size_t)l * CC * CC, CC, CC,
                                                     wf2 + (size_t)l * CC * CC);
        }
    }

    // fixed positional attention map (fp16)
    a2_sum_k<<<1, 256>>>(arow);
    a2_fill_k<<<T, 256>>>(arow, a2);

    const long long rowstr = (long long)T * 4 * CC;   // qkvt batch row stride per bn
    for (int l = 0; l < LDEP; l++) {
        ln_k<<<MALL / 8, 256>>>(h, z, ln1_g + l * CC, ln1_b + l * CC);
        // qkvt = z @ W_qkv[l] -> fp16 (M=40960, N=2048, K=512)
        mma_gemm<4><<<dim3(4 * CC / 128, MALL / 128), 256, MM_SMEM>>>(
            z, CC, 0, wqkv + (size_t)l * 4 * CC * CC,
            CC, CC, 1.f, nullptr, qkvt, 4 * CC, nullptr, 1, 0, 0, 0, 0, 0, 0);
        // S = scale * Q @ K^T  (batched bn x H, M=N=256, K=128); K block at col offset CC
        mma_gemm<0><<<dim3(2, 2, BNB * H), 256, MM_SMEM>>>(
            qkvt, 4 * CC, 0, qkvt + CC, 4 * CC, DH, scale,
            S, nullptr, T, nullptr,
            H, rowstr, DH, rowstr, DH, (long long)H * T * T, (long long)T * T);
        softmax_k<<<BNB * H * T / 8, 256>>>(S, Shp);
        // transpose V and T head blocks to [bn,h,d,t]
        trans_vt2<<<dim3(DH / 32, T / 32, 2 * BNB * H), dim3(16, 16)>>>(qkvt, vt, tt);
        // o1 = S @ V  (batched bn x H, M=256, N=128, K=256)
        mma_gemm<4><<<dim3(1, 2, BNB * H), 256, MM_SMEM>>>(
            Shp, T, 0, vt, T, T, 1.f,
            nullptr, O, 2 * CC, nullptr,
            H, (long long)H * T * T, (long long)T * T,
            (long long)H * DH * T, (long long)DH * T,
            (long long)T * 2 * CC, 2 * DH);
        // o2 = a2 @ Tm
        mma_gemm<4><<<dim3(1, 2, BNB * H), 256, MM_SMEM>>>(
            a2, T, 0, tt, T, T, 1.f,
            nullptr, O + DH, 2 * CC, nullptr,
            H, 0, 0,
            (long long)H * DH * T, (long long)DH * T,
            (long long)T * 2 * CC, 2 * DH);
        // h = O @ W_o[l] + b_o + h   (M=40960, N=512, K=1024)
        mma_gemm<2><<<dim3(CC / 128, MALL / 128), 256, MM_SMEM>>>(
            O, 2 * CC, 0, wo + (size_t)l * CC * 2 * CC,
            2 * CC, 2 * CC, 1.f, h, nullptr, CC, b_o + l * CC, 1, 0, 0, 0, 0, 0, 0);
        // FF
        ln_k<<<MALL / 8, 256>>>(h, z, ln2_g + l * CC, ln2_b + l * CC);
        mma_gemm<3><<<dim3(CC / 128, MALL / 128), 256, MM_SMEM>>>(
            z, CC, 0, wf1 + (size_t)l * CC * CC,
            CC, CC, 1.f, nullptr, f1, CC, b_f1 + l * CC, 1, 0, 0, 0, 0, 0, 0);
        mma_gemm<2><<<dim3(CC / 128, MALL / 128), 256, MM_SMEM>>>(
            f1, CC, 0, wf2 + (size_t)l * CC * CC,
            CC, CC, 1.f, h, nullptr, CC, b_f2 + l * CC, 1, 0, 0, 0, 0, 0, 0);
    }

    // head
    tr1_k<<<(CC * 32 + 255) / 256, 256>>>(c1_W, w1t);
    tr2_k<<<2, 256>>>(c2_W, w2t);
    head_k<<<MALL / 8, 256>>>(h, w1t, c1_b, bn1_g, bn1_b, bn1_m, bn1_v,
                              w2t, c2_b, bn2_g, bn2_b, bn2_m, bn2_v,
                              c3_W, c3_b, score, dist);
    final_k<<<(BATCH * T + 255) / 256, 256>>>(dist, score, out);
}

// round 16
// speedup vs baseline: 3.3097x; 1.1109x over previous
#include <cuda_runtime.h>
#include <cuda_fp16.h>
#include <math.h>
#include <stdint.h>

// Problem constants
constexpr int BATCH = 16, NCROP = 10, BNB = 160, T = 256, D = 1024, CC = 512;
constexpr int H = 4, DH = 128, LDEP = 2;
constexpr int MALL = BNB * T;               // 40960 rows
constexpr float EPS = 1e-5f;

// ---------------- device scratch (static, no allocation) ----------------
__device__ __align__(16) __half g_xp[(size_t)BNB * (T + 2) * D];
__device__ __align__(16) __half g_bte[CC * 3 * D];
__device__ __align__(16) __half g_z[(size_t)MALL * CC];
__device__ __align__(16) __half g_f1[(size_t)MALL * CC];
__device__ __align__(16) __half g_O[(size_t)MALL * 2 * CC];
__device__ __align__(16) __half g_qkvt[(size_t)MALL * 4 * CC];
__device__ __align__(16) __half g_Sh[(size_t)BNB * H * T * T];
__device__ __align__(16) __half g_vt[(size_t)BNB * H * DH * T];
__device__ __align__(16) __half g_tt[(size_t)BNB * H * DH * T];
__device__ __align__(16) __half g_a2[T * T];
__device__ __align__(16) __half g_wqkv[LDEP * 4 * CC * CC];
__device__ __align__(16) __half g_wo[LDEP * CC * 2 * CC];
__device__ __align__(16) __half g_wf1[LDEP * CC * CC];
__device__ __align__(16) __half g_wf2[LDEP * CC * CC];
// fp32 buffers
__device__ __align__(16) float g_h[(size_t)MALL * CC];
__device__ __align__(16) float g_S[(size_t)BNB * H * T * T];
__device__ float g_arow[T];
__device__ float g_w1t[CC * 32];
__device__ float g_w2t[32 * 16];
__device__ float g_score[MALL];
__device__ float g_dist[MALL];

// ---------------- helpers ----------------
__device__ __forceinline__ uint32_t smem_u32(const void* p) {
    uint32_t a;
    asm("{ .reg .u64 t; cvta.to.shared.u64 t, %1; cvt.u32.u64 %0, t; }" : "=r"(a) : "l"(p));
    return a;
}
__device__ __forceinline__ void cp16(uint32_t dst, const void* src) {
    asm volatile("cp.async.cg.shared.global [%0], [%1], 16;" :: "r"(dst), "l"(src));
}
__device__ __forceinline__ void cp_commit() {
    asm volatile("cp.async.commit_group;" ::: "memory");
}
template<int N>
__device__ __forceinline__ void cp_wait() {
    asm volatile("cp.async.wait_group %0;" :: "n"(N) : "memory");
}
__device__ __forceinline__ void ldsm4(uint32_t& r0, uint32_t& r1, uint32_t& r2, uint32_t& r3, uint32_t addr) {
    asm volatile("ldmatrix.sync.aligned.m8n8.x4.shared.b16 {%0,%1,%2,%3}, [%4];"
                 : "=r"(r0), "=r"(r1), "=r"(r2), "=r"(r3) : "r"(addr));
}
__device__ __forceinline__ void mma16816(float* c, const uint32_t* a, const uint32_t* b) {
    asm volatile(
        "mma.sync.aligned.m16n8k16.row.col.f32.f16.f16.f32 "
        "{%0,%1,%2,%3}, {%4,%5,%6,%7}, {%8,%9}, {%0,%1,%2,%3};"
        : "+f"(c[0]), "+f"(c[1]), "+f"(c[2]), "+f"(c[3])
        : "r"(a[0]), "r"(a[1]), "r"(a[2]), "r"(a[3]), "r"(b[0]), "r"(b[1]));
}

// ================= plain fp16 HMMA GEMM: C(M,N) = alpha * A(M,K) @ B(N,K)^T =================
// 128x128 CTA tile, 8 warps of 64x32, BK=64, cp.async double buffer, two-level batch, 2 CTA/SM.
// EPI: 0 fp32 store (alpha); 1 +bias relu fp32; 2 +bias +C fp32; 3 +bias gelu fp16; 4 plain fp16.
constexpr int LDS64 = 72;                    // halves per smem row (64 data + 8 pad)
constexpr int TILE_B = 128 * LDS64 * 2;      // 18432 bytes per tile
constexpr int STAGE_B = 2 * TILE_B;          // A, B
constexpr int MM_SMEM = 2 * STAGE_B;         // 73728

template<int EPI>
__global__ void __launch_bounds__(256, 2) mma_gemm(
    const __half* __restrict__ A, int lda, int convA,
    const __half* __restrict__ B, int ldb, int K, float alpha,
    float* __restrict__ C, __half* __restrict__ Ch,
    int ldc, const float* __restrict__ bias,
    int H2, long long sA1, long long sA2, long long sB1, long long sB2,
    long long sC1, long long sC2)
{
    extern __shared__ __align__(1024) char smem[];
    const uint32_t sbase = smem_u32(smem);
    const int tid = threadIdx.x, lane = tid & 31, wid = tid >> 5;
    const int bz = blockIdx.z;
    const int b1 = bz / H2, b2 = bz - b1 * H2;
    const int m0 = blockIdx.y * 128, n0 = blockIdx.x * 128;
    const int wm = (wid & 1) * 64, wn = (wid >> 1) * 32;

    const __half* baseA = A + ((size_t)b1 * sA1 + (size_t)b2 * sA2);
    const __half* baseB = B + ((size_t)b1 * sB1 + (size_t)b2 * sB2);
    const size_t cbase = (size_t)b1 * sC1 + (size_t)b2 * sC2;

    // load plan: 8 chunks of 16B per thread (4 for A tile, 4 for B tile); 8 chunks/row
    uint32_t aoff32[4], boff32[4], sdoff[8];
    #pragma unroll
    for (int q = 0; q < 4; q++) {
        int ci = q * 256 + tid;
        int r = ci >> 3, c16 = ci & 7;
        sdoff[q] = (uint32_t)(r * (LDS64 * 2) + c16 * 16);
        int gr = m0 + r;
        aoff32[q] = (uint32_t)(gr * lda + (convA ? (gr >> 8) * 2048 : 0) + c16 * 8);
    }
    #pragma unroll
    for (int q = 0; q < 4; q++) {
        int ci = q * 256 + tid;
        int r = ci >> 3, c16 = ci & 7;
        sdoff[4 + q] = (uint32_t)(TILE_B + r * (LDS64 * 2) + c16 * 16);
        boff32[q] = (uint32_t)((n0 + r) * ldb + c16 * 8);
    }

    const int nc = K / 64;
    #pragma unroll
    for (int q = 0; q < 4; q++) cp16(sbase + sdoff[q], baseA + aoff32[q]);
    #pragma unroll
    for (int q = 0; q < 4; q++) cp16(sbase + sdoff[4 + q], baseB + boff32[q]);
    cp_commit();

    float acc[4][4][4] = {};
    const int lrowA = lane & 15, lkA = (lane >> 4) << 3;
    const int lrowB = ((lane >> 4) << 3) + (lane & 7), lkB = ((lane >> 3) & 1) << 3;

    for (int c = 0; c < nc; c++) {
        if (c + 1 < nc) {
            uint32_t st = sbase + (uint32_t)(((c + 1) & 1) * STAGE_B);
            uint32_t k0 = (uint32_t)((c + 1) * 64);
            #pragma unroll
            for (int q = 0; q < 4; q++) cp16(st + sdoff[q], baseA + aoff32[q] + k0);
            #pragma unroll
            for (int q = 0; q < 4; q++) cp16(st + sdoff[4 + q], baseB + boff32[q] + k0);
            cp_commit();
            cp_wait<1>();
        } else {
            cp_wait<0>();
        }
        __syncthreads();

        uint32_t sa = sbase + (uint32_t)((c & 1) * STAGE_B);
        #pragma unroll
        for (int kk2 = 0; kk2 < 4; kk2++) {
            const int kk = kk2 * 16;
            uint32_t af[4][4], bf[4][2];
            #pragma unroll
            for (int mt = 0; mt < 4; mt++) {
                uint32_t ra = sa + (uint32_t)((wm + mt * 16 + lrowA) * (LDS64 * 2) + (kk + lkA) * 2);
                ldsm4(af[mt][0], af[mt][1], af[mt][2], af[mt][3], ra);
            }
            #pragma unroll
            for (int np = 0; np < 2; np++) {
                uint32_t rb = sa + (uint32_t)(TILE_B + (wn + np * 16 + lrowB) * (LDS64 * 2) + (kk + lkB) * 2);
                uint32_t h0, h1, h2, h3;
                ldsm4(h0, h1, h2, h3, rb);
                bf[np * 2][0] = h0; bf[np * 2][1] = h1;
                bf[np * 2 + 1][0] = h2; bf[np * 2 + 1][1] = h3;
            }
            #pragma unroll
            for (int mt = 0; mt < 4; mt++)
                #pragma unroll
                for (int nt = 0; nt < 4; nt++)
                    mma16816(acc[mt][nt], af[mt], bf[nt]);
        }
        __syncthreads();
    }

    const int qr = lane >> 2, qc = (lane & 3) * 2;
    #pragma unroll
    for (int mt = 0; mt < 4; mt++) {
        #pragma unroll
        for (int hrow = 0; hrow < 2; hrow++) {
            int grow = m0 + wm + mt * 16 + qr + hrow * 8;
            #pragma unroll
            for (int nt = 0; nt < 4; nt++) {
                int gcol = n0 + wn + nt * 8 + qc;
                float v0 = acc[mt][nt][hrow * 2 + 0] * alpha;
                float v1 = acc[mt][nt][hrow * 2 + 1] * alpha;
                if (EPI == 1 || EPI == 2 || EPI == 3) { v0 += bias[gcol]; v1 += bias[gcol + 1]; }
                if (EPI == 1) { v0 = fmaxf(v0, 0.f); v1 = fmaxf(v1, 0.f); }
                if (EPI == 3) {
                    v0 = 0.5f * v0 * (1.f + erff(v0 * 0.70710678118654752f));
                    v1 = 0.5f * v1 * (1.f + erff(v1 * 0.70710678118654752f));
                }
                size_t off = cbase + (size_t)grow * ldc + gcol;
                if (EPI == 3 || EPI == 4) {
                    __half2 ph; ph.x = __float2half(v0); ph.y = __float2half(v1);
                    *reinterpret_cast<__half2*>(Ch + off) = ph;
                } else {
                    if (EPI == 2) {
                        float2 old = *reinterpret_cast<const float2*>(C + off);
                        v0 += old.x; v1 += old.y;
                    }
                    float2 o; o.x = v0; o.y = v1;
                    *reinterpret_cast<float2*>(C + off) = o;
                }
            }
        }
    }
}

// ---------------- transpose V+T head blocks, half2-vectorized ----------------
__global__ void trans_vt2(const __half* __restrict__ srch,
                          __half* __restrict__ vd, __half* __restrict__ td) {
    __shared__ __half sh[32][34];
    int zz = blockIdx.z;
    int sel = zz >= BNB * H;
    int z = zz - sel * BNB * H;
    int bn = z >> 2, hh = z & 3;
    int coloff = 2 * CC + sel * CC;
    __half* dst = sel ? td : vd;
    int d0 = blockIdx.x * 32, t0 = blockIdx.y * 32;
    int tx = threadIdx.x;
    int ty = threadIdx.y;
    #pragma unroll
    for (int j = 0; j < 2; j++) {
        int tl = ty + j * 16;
        __half2 v = *reinterpret_cast<const __half2*>(
            srch + ((size_t)(bn * T + t0 + tl)) * 2048 + coloff + hh * 128 + d0 + 2 * tx);
        sh[tl][2 * tx] = v.x;
        sh[tl][2 * tx + 1] = v.y;
    }
    __syncthreads();
    #pragma unroll
    for (int j = 0; j < 2; j++) {
        int dl = ty + j * 16;
        __half2 o;
        o.x = sh[2 * tx][dl];
        o.y = sh[2 * tx + 1][dl];
        *reinterpret_cast<__half2*>(dst + ((size_t)z * DH + d0 + dl) * T + t0 + 2 * tx) = o;
    }
}

// ---------------- vectorized pad (float4 -> 4 halves) ----------------
__global__ void pad_k(const float* __restrict__ x, __half* __restrict__ xp) {
    size_t total4 = (size_t)BNB * (T + 2) * D / 4;
    const int ROW4 = D / 4;
    for (size_t idx = (size_t)blockIdx.x * blockDim.x + threadIdx.x; idx < total4;
         idx += (size_t)gridDim.x * blockDim.x) {
        size_t bn = idx / ((T + 2) * ROW4);
        size_t rr = idx - bn * (T + 2) * ROW4;
        int tt = (int)(rr / ROW4);
        int i4 = (int)(rr - (size_t)tt * ROW4);
        __half2 h0, h1;
        if (tt == 0 || tt == T + 1) {
            h0.x = __float2half(0.f); h0.y = h0.x; h1 = h0;
        } else {
            float4 v = *reinterpret_cast<const float4*>(x + ((bn * T + (tt - 1)) * (size_t)D + i4 * 4));
            h0 = __floats2half2_rn(v.x, v.y);
            h1 = __floats2half2_rn(v.z, v.w);
        }
        __half2* dst = reinterpret_cast<__half2*>(xp) + idx * 2;
        dst[0] = h0; dst[1] = h1;
    }
}

__global__ void csplit_k(const float* __restrict__ W, __half* __restrict__ o) {
    int total = CC * 3 * D;
    for (int idx = blockIdx.x * blockDim.x + threadIdx.x; idx < total; idx += gridDim.x * blockDim.x) {
        int c = idx / (3 * D), j = idx % (3 * D);
        int kk = j >> 10, i = j & 1023;
        o[idx] = __float2half(W[(size_t)c * 3 * D + i * 3 + kk]);
    }
}

// ---------------- merged weight transpose+convert: all layers, all 4 weight groups ----------
__global__ void wsplit_all(const float* __restrict__ Wqkv, const float* __restrict__ Wo,
                           const float* __restrict__ Wf1, const float* __restrict__ Wf2,
                           __half* __restrict__ oqkv, __half* __restrict__ owo,
                           __half* __restrict__ of1, __half* __restrict__ of2) {
    const int QKV = 4 * CC * CC;        // 1048576
    const int WO  = 2 * CC * CC;        // 524288
    const int F   = CC * CC;            // 262144
    const int PER_L = QKV + WO + 2 * F; // 2097152
    int total = LDEP * PER_L;
    for (int idx = blockIdx.x * blockDim.x + threadIdx.x; idx < total; idx += gridDim.x * blockDim.x) {
        int l = idx / PER_L;
        int r = idx - l * PER_L;
        const float* W; __half* o; int N, K, base;
        if (r < QKV)            { W = Wqkv + (size_t)l * QKV; o = oqkv + (size_t)l * QKV; N = 4 * CC; K = CC;    base = r; }
        else if (r < QKV + WO)  { W = Wo  + (size_t)l * WO;  o = owo  + (size_t)l * WO;  N = CC;     K = 2 * CC; base = r - QKV; }
        else if (r < QKV + WO + F) { W = Wf1 + (size_t)l * F; o = of1 + (size_t)l * F;   N = CC;     K = CC;    base = r - QKV - WO; }
        else                    { W = Wf2 + (size_t)l * F;   o = of2 + (size_t)l * F;    N = CC;     K = CC;    base = r - QKV - WO - F; }
        int n = base / K, k = base - n * K;
        o[base] = __float2half(W[(size_t)k * N + n]);
    }
}

__global__ void a2_sum_k(float* __restrict__ srow) {
    int j = threadIdx.x;
    float s = 0.f;
    for (int k = 0; k < T; k++)
        s += expf(-fabsf((float)(j - k)) / 2.718281828459045f);
    srow[j] = s;
}
__global__ void a2_fill_k(const float* __restrict__ srow, __half* __restrict__ a2) {
    int i = blockIdx.x, j = threadIdx.x;
    float v = expf(-fabsf((float)(i - j)) / 2.718281828459045f) / srow[j];
    a2[i * T + j] = __float2half(v);
}
__global__ void tr1_k(const float* __restrict__ W, float* __restrict__ Wt) {
    int idx = blockIdx.x * blockDim.x + threadIdx.x;
    if (idx < CC * 32) { int c = idx / 32, o = idx % 32; Wt[idx] = W[o * CC + c]; }
}
__global__ void tr2_k(const float* __restrict__ W, float* __restrict__ Wt) {
    int idx = blockIdx.x * blockDim.x + threadIdx.x;
    if (idx < 32 * 16) { int c = idx / 16, o = idx % 16; Wt[idx] = W[o * 32 + c]; }
}

// ---------------- LayerNorm: warp per row, shuffle-only, float4 I/O ----------------
__global__ void ln_k(const float* __restrict__ X, __half* __restrict__ Y,
                     const float* __restrict__ g, const float* __restrict__ b) {
    int warp = threadIdx.x >> 5, lane = threadIdx.x & 31;
    size_t row = (size_t)blockIdx.x * 8 + warp;
    const float4* x4 = reinterpret_cast<const float4*>(X + row * CC);
    float4 v[4];
    float s = 0.f;
    #pragma unroll
    for (int k = 0; k < 4; k++) {
        v[k] = x4[k * 32 + lane];
        s += v[k].x + v[k].y + v[k].z + v[k].w;
    }
    #pragma unroll
    for (int o = 16; o; o >>= 1) s += __shfl_xor_sync(0xffffffffu, s, o);
    float mean = s * (1.f / CC);
    float q = 0.f;
    #pragma unroll
    for (int k = 0; k < 4; k++) {
        float a0 = v[k].x - mean, a1 = v[k].y - mean, a2 = v[k].z - mean, a3 = v[k].w - mean;
        q += a0 * a0 + a1 * a1 + a2 * a2 + a3 * a3;
    }
    #pragma unroll
    for (int o = 16; o; o >>= 1) q += __shfl_xor_sync(0xffffffffu, q, o);
    float rstd = rsqrtf(q * (1.f / CC) + EPS);
    __half2* y2 = reinterpret_cast<__half2*>(Y + row * CC);
    const float4* g4 = reinterpret_cast<const float4*>(g);
    const float4* b4 = reinterpret_cast<const float4*>(b);
    #pragma unroll
    for (int k = 0; k < 4; k++) {
        int idx = k * 32 + lane;
        float4 gg = g4[idx], bb = b4[idx];
        float y0 = (v[k].x - mean) * rstd * gg.x + bb.x;
        float y1 = (v[k].y - mean) * rstd * gg.y + bb.y;
        float y2v = (v[k].z - mean) * rstd * gg.z + bb.z;
        float y3 = (v[k].w - mean) * rstd * gg.w + bb.w;
        y2[idx * 2]     = __floats2half2_rn(y0, y1);
        y2[idx * 2 + 1] = __floats2half2_rn(y2v, y3);
    }
}

// ---------------- softmax: warp per row of 256, shuffle-only ----------------
__global__ void softmax_k(const float* __restrict__ S, __half* __restrict__ Sh) {
    int warp = threadIdx.x >> 5, lane = threadIdx.x & 31;
    size_t row = (size_t)blockIdx.x * 8 + warp;
    const float4* p4 = reinterpret_cast<const float4*>(S + row * T);
    float4 a = p4[lane], b = p4[32 + lane];
    float mx = fmaxf(fmaxf(fmaxf(a.x, a.y), fmaxf(a.z, a.w)),
                     fmaxf(fmaxf(b.x, b.y), fmaxf(b.z, b.w)));
    #pragma unroll
    for (int o = 16; o; o >>= 1) mx = fmaxf(mx, __shfl_xor_sync(0xffffffffu, mx, o));
    float e[8];
    e[0] = expf(a.x - mx); e[1] = expf(a.y - mx); e[2] = expf(a.z - mx); e[3] = expf(a.w - mx);
    e[4] = expf(b.x - mx); e[5] = expf(b.y - mx); e[6] = expf(b.z - mx); e[7] = expf(b.w - mx);
    float s = e[0] + e[1] + e[2] + e[3] + e[4] + e[5] + e[6] + e[7];
    #pragma unroll
    for (int o = 16; o; o >>= 1) s += __shfl_xor_sync(0xffffffffu, s, o);
    float inv = 1.f / s;
    __half2* o2 = reinterpret_cast<__half2*>(Sh + row * T);
    o2[lane * 2]           = __floats2half2_rn(e[0] * inv, e[1] * inv);
    o2[lane * 2 + 1]       = __floats2half2_rn(e[2] * inv, e[3] * inv);
    o2[(32 + lane) * 2]     = __floats2half2_rn(e[4] * inv, e[5] * inv);
    o2[(32 + lane) * 2 + 1] = __floats2half2_rn(e[6] * inv, e[7] * inv);
}

// ---------------- fused head ----------------
__global__ void head_k(const float* __restrict__ Hh,
                       const float* __restrict__ W1t, const float* __restrict__ c1_b,
                       const float* __restrict__ bn1_g, const float* __restrict__ bn1_b,
                       const float* __restrict__ bn1_m, const float* __restrict__ bn1_v,
                       const float* __restrict__ W2t, const float* __restrict__ c2_b,
                       const float* __restrict__ bn2_g, const float* __restrict__ bn2_b,
                       const float* __restrict__ bn2_m, const float* __restrict__ bn2_v,
                       const float* __restrict__ c3_W, const float* __restrict__ c3_b,
                       float* __restrict__ score, float* __restrict__ dist) {
    int warp = threadIdx.x >> 5, lane = threadIdx.x & 31;
    size_t row = (size_t)blockIdx.x * 8 + warp;
    __shared__ float hs[8][CC];
    for (int idx = threadIdx.x; idx < 8 * CC; idx += 256) {
        int r = idx >> 9, c = idx & (CC - 1);
        hs[r][c] = Hh[((size_t)blockIdx.x * 8 + r) * CC + c];
    }
    __syncthreads();
    int o = lane;
    float x1 = c1_b[o];
    #pragma unroll 8
    for (int c = 0; c < CC; c++)
        x1 = fmaf(hs[warp][c], W1t[c * 32 + o], x1);
    float dd = x1 - bn1_m[o];
    float d1 = dd * dd / bn1_v[o];
    #pragma unroll
    for (int s = 16; s; s >>= 1) d1 += __shfl_xor_sync(0xffffffffu, d1, s);
    float y1 = fmaxf((x1 - bn1_m[o]) * rsqrtf(bn1_v[o] + EPS) * bn1_g[o] + bn1_b[o], 0.f);
    float x2 = (lane < 16) ? c2_b[lane] : 0.f;
    #pragma unroll
    for (int c = 0; c < 32; c++) {
        float yc = __shfl_sync(0xffffffffu, y1, c);
        if (lane < 16) x2 = fmaf(yc, W2t[c * 16 + lane], x2);
    }
    float d2 = 0.f;
    if (lane < 16) { float e = x2 - bn2_m[lane]; d2 = e * e / bn2_v[lane]; }
    #pragma unroll
    for (int s = 16; s; s >>= 1) d2 += __shfl_xor_sync(0xffffffffu, d2, s);
    float y2 = 0.f;
    if (lane < 16)
        y2 = fmaxf((x2 - bn2_m[lane]) * rsqrtf(bn2_v[lane] + EPS) * bn2_g[lane] + bn2_b[lane], 0.f);
    float sacc = (lane < 16) ? y2 * c3_W[lane] : 0.f;
    #pragma unroll
    for (int s = 16; s; s >>= 1) sacc += __shfl_xor_sync(0xffffffffu, sacc, s);
    if (lane == 0) {
        score[row] = 1.f / (1.f + expf(-(sacc + c3_b[0])));
        dist[row] = sqrtf(d1) + sqrtf(d2);
    }
}

__global__ void final_k(const float* __restrict__ dist, const float* __restrict__ score,
                        float* __restrict__ out) {
    int idx = blockIdx.x * blockDim.x + threadIdx.x;
    if (idx >= BATCH * T) return;
    int b = idx / T, t = idx % T;
    float sd = 0.f, ss = 0.f;
    for (int n = 0; n < NCROP; n++) {
        size_t r = ((size_t)(b * NCROP + n)) * T + t;
        sd += dist[r];
        ss += score[r];
    }
    out[idx] = (sd * 0.1f) * (ss * 0.1f);
}

// ---------------- host launch ----------------
template<typename P>
static P symaddr_t(const void* sym) {
    void* p = nullptr;
    cudaGetSymbolAddress(&p, sym);
    return (P)p;
}

extern "C" void kernel_launch(void* const* d_in, const int* in_sizes, int n_in,
                              void* d_out, int out_size) {
    const float* x     = (const float*)d_in[0];
    const float* W_emb = (const float*)d_in[1];
    const float* b_emb = (const float*)d_in[2];
    const float* ln1_g = (const float*)d_in[3];
    const float* ln1_b = (const float*)d_in[4];
    const float* W_qkv = (const float*)d_in[5];
    const float* W_o   = (const float*)d_in[6];
    const float* b_o   = (const float*)d_in[7];
    const float* ln2_g = (const float*)d_in[8];
    const float* ln2_b = (const float*)d_in[9];
    const float* W_f1  = (const float*)d_in[10];
    const float* b_f1  = (const float*)d_in[11];
    const float* W_f2  = (const float*)d_in[12];
    const float* b_f2  = (const float*)d_in[13];
    const float* c1_W  = (const float*)d_in[14];
    const float* c1_b  = (const float*)d_in[15];
    const float* bn1_g = (const float*)d_in[16];
    const float* bn1_b = (const float*)d_in[17];
    const float* bn1_m = (const float*)d_in[18];
    const float* bn1_v = (const float*)d_in[19];
    const float* c2_W  = (const float*)d_in[20];
    const float* c2_b  = (const float*)d_in[21];
    const float* bn2_g = (const float*)d_in[22];
    const float* bn2_b = (const float*)d_in[23];
    const float* bn2_m = (const float*)d_in[24];
    const float* bn2_v = (const float*)d_in[25];
    const float* c3_W  = (const float*)d_in[26];
    const float* c3_b  = (const float*)d_in[27];
    float* out = (float*)d_out;

    __half* xp = symaddr_t<__half*>(g_xp);
    __half* bte = symaddr_t<__half*>(g_bte);
    __half* z = symaddr_t<__half*>(g_z);
    __half* f1 = symaddr_t<__half*>(g_f1);
    __half* O = symaddr_t<__half*>(g_O);
    __half* qkvt = symaddr_t<__half*>(g_qkvt);
    __half* Shp = symaddr_t<__half*>(g_Sh);
    __half* vt = symaddr_t<__half*>(g_vt);
    __half* tt = symaddr_t<__half*>(g_tt);
    __half* a2 = symaddr_t<__half*>(g_a2);
    __half* wqkv = symaddr_t<__half*>(g_wqkv);
    __half* wo = symaddr_t<__half*>(g_wo);
    __half* wf1 = symaddr_t<__half*>(g_wf1);
    __half* wf2 = symaddr_t<__half*>(g_wf2);
    float* h    = symaddr_t<float*>(g_h);
    float* S    = symaddr_t<float*>(g_S);
    float* arow = symaddr_t<float*>(g_arow);
    float* w1t  = symaddr_t<float*>(g_w1t);
    float* w2t  = symaddr_t<float*>(g_w2t);
    float* score = symaddr_t<float*>(g_score);
    float* dist  = symaddr_t<float*>(g_dist);

    const float scale = 0.08838834764831845f;  // 1/sqrt(128)
    cudaFuncSetAttribute(mma_gemm<0>, cudaFuncAttributeMaxDynamicSharedMemorySize, MM_SMEM);
    cudaFuncSetAttribute(mma_gemm<1>, cudaFuncAttributeMaxDynamicSharedMemorySize, MM_SMEM);
    cudaFuncSetAttribute(mma_gemm<2>, cudaFuncAttributeMaxDynamicSharedMemorySize, MM_SMEM);
    cudaFuncSetAttribute(mma_gemm<3>, cudaFuncAttributeMaxDynamicSharedMemorySize, MM_SMEM);
    cudaFuncSetAttribute(mma_gemm<4>, cudaFuncAttributeMaxDynamicSharedMemorySize, MM_SMEM);

    // prep ordered so conv GEMM is my 4th launch (ncu capture target)
    {
        size_t total4 = (size_t)BNB * (T + 2) * D / 4;
        pad_k<<<(int)((total4 + 255) / 256), 256>>>(x, xp);                            // 1
        csplit_k<<<(3 * D * CC + 255) / 256, 256>>>(W_emb, bte);                       // 2
        wsplit_all<<<(LDEP * 2097152 + 255) / 256, 256>>>(W_qkv, W_o, W_f1, W_f2,      // 3
                                                          wqkv, wo, wf1, wf2);
        // conv-as-GEMM: M=40960, N=512, K=3072 (overlapping-window A)                 // 4 <- profiled
        mma_gemm<1><<<dim3(CC / 128, MALL / 128), 256, MM_SMEM>>>(
            xp, 1024, 1, bte, 3 * D, 3 * D, 1.f,
            h, nullptr, CC, b_emb, 1, 0, 0, 0, 0, 0, 0);
    }

    // fixed positional attention map (fp16)
    a2_sum_k<<<1, 256>>>(arow);
    a2_fill_k<<<T, 256>>>(arow, a2);

    const long long rowstr = (long long)T * 4 * CC;   // qkvt batch row stride per bn
    for (int l = 0; l < LDEP; l++) {
        ln_k<<<MALL / 8, 256>>>(h, z, ln1_g + l * CC, ln1_b + l * CC);
        // qkvt = z @ W_qkv[l] -> fp16 (M=40960, N=2048, K=512)
        mma_gemm<4><<<dim3(4 * CC / 128, MALL / 128), 256, MM_SMEM>>>(
            z, CC, 0, wqkv + (size_t)l * 4 * CC * CC,
            CC, CC, 1.f, nullptr, qkvt, 4 * CC, nullptr, 1, 0, 0, 0, 0, 0, 0);
        // S = scale * Q @ K^T  (batched bn x H, M=N=256, K=128); K block at col offset CC
        mma_gemm<0><<<dim3(2, 2, BNB * H), 256, MM_SMEM>>>(
            qkvt, 4 * CC, 0, qkvt + CC, 4 * CC, DH, scale,
            S, nullptr, T, nullptr,
            H, rowstr, DH, rowstr, DH, (long long)H * T * T, (long long)T * T);
        softmax_k<<<BNB * H * T / 8, 256>>>(S, Shp);
        // transpose V and T head blocks to [bn,h,d,t]
        trans_vt2<<<dim3(DH / 32, T / 32, 2 * BNB * H), dim3(16, 16)>>>(qkvt, vt, tt);
        // o1 = S @ V  (batched bn x H, M=256, N=128, K=256)
        mma_gemm<4><<<dim3(1, 2, BNB * H), 256, MM_SMEM>>>(
            Shp, T, 0, vt, T, T, 1.f,
            nullptr, O, 2 * CC, nullptr,
            H, (long long)H * T * T, (long long)T * T,
            (long long)H * DH * T, (long long)DH * T,
            (long long)T * 2 * CC, 2 * DH);
        // o2 = a2 @ Tm
        mma_gemm<4><<<dim3(1, 2, BNB * H), 256, MM_SMEM>>>(
            a2, T, 0, tt, T, T, 1.f,
            nullptr, O + DH, 2 * CC, nullptr,
            H, 0, 0,
            (long long)H * DH * T, (long long)DH * T,
            (long long)T * 2 * CC, 2 * DH);
        // h = O @ W_o[l] + b_o + h   (M=40960, N=512, K=1024)
        mma_gemm<2><<<dim3(CC / 128, MALL / 128), 256, MM_SMEM>>>(
            O, 2 * CC, 0, wo + (size_t)l * CC * 2 * CC,
            2 * CC, 2 * CC, 1.f, h, nullptr, CC, b_o + l * CC, 1, 0, 0, 0, 0, 0, 0);
        // FF
        ln_k<<<MALL / 8, 256>>>(h, z, ln2_g + l * CC, ln2_b + l * CC);
        mma_gemm<3><<<dim3(CC / 128, MALL / 128), 256, MM_SMEM>>>(
            z, CC, 0, wf1 + (size_t)l * CC * CC,
            CC, CC, 1.f, nullptr, f1, CC, b_f1 + l * CC, 1, 0, 0, 0, 0, 0, 0);
        mma_gemm<2><<<dim3(CC / 128, MALL / 128), 256, MM_SMEM>>>(
            f1, CC, 0, wf2 + (size_t)l * CC * CC,
            CC, CC, 1.f, h, nullptr, CC, b_f2 + l * CC, 1, 0, 0, 0, 0, 0, 0);
    }

    // head
    tr1_k<<<(CC * 32 + 255) / 256, 256>>>(c1_W, w1t);
    tr2_k<<<2, 256>>>(c2_W, w2t);
    head_k<<<MALL / 8, 256>>>(h, w1t, c1_b, bn1_g, bn1_b, bn1_m, bn1_v,
                              w2t, c2_b, bn2_g, bn2_b, bn2_m, bn2_v,
                              c3_W, c3_b, score, dist);
    final_k<<<(BATCH * T + 255) / 256, 256>>>(dist, score, out);
}